// round 4
// baseline (speedup 1.0000x reference)
#include <cuda_runtime.h>

// Problem constants
#define DM 1024
#define TT 2048
#define NB 4
#define NH 16
#define DK 64

// Scratch: __device__ globals (allocation inside kernel_launch is forbidden)
__device__ float g_Q[NB * TT * DM];
__device__ float g_K[NB * TT * DM];
__device__ float g_V[NB * TT * DM];
__device__ float g_A[NB * TT * DM];

// ---------------------------------------------------------------------------
// helpers
// ---------------------------------------------------------------------------
__device__ __forceinline__ unsigned f2tf(float x) {
    unsigned u;
    asm("cvt.rna.tf32.f32 %0, %1;" : "=r"(u) : "f"(x));
    return u;
}

__device__ __forceinline__ void mma8(float (&d)[4], const unsigned (&a)[4],
                                     unsigned b0, unsigned b1) {
    asm volatile(
        "mma.sync.aligned.m16n8k8.row.col.f32.tf32.tf32.f32 "
        "{%0,%1,%2,%3}, {%4,%5,%6,%7}, {%8,%9}, {%0,%1,%2,%3};"
        : "+f"(d[0]), "+f"(d[1]), "+f"(d[2]), "+f"(d[3])
        : "r"(a[0]), "r"(a[1]), "r"(a[2]), "r"(a[3]), "r"(b0), "r"(b1));
}

__device__ __forceinline__ void cpa16(void* s, const void* g) {
    unsigned sa = (unsigned)__cvta_generic_to_shared(s);
    asm volatile("cp.async.cg.shared.global [%0], [%1], 16;" ::"r"(sa), "l"(g));
}
#define CP_COMMIT asm volatile("cp.async.commit_group;")
#define CP_WAIT(n) asm volatile("cp.async.wait_group %0;" ::"n"(n))

// ---------------------------------------------------------------------------
// GEMM: C[8192,1024] = A[8192,1024] @ W[1024,1024]^T + bias  (torch y = xW^T)
// Block tile 128x64, BK=16, 256 threads (8 warps, 32x32 warp tiles), tf32 mma.
// Smem row stride 28 floats (28 mod 32 -> conflict-free fragment LDS).
// ---------------------------------------------------------------------------
#define GBM 128
#define GBN 64
#define GBK 16
#define AST 28

__global__ __launch_bounds__(256, 2) void gemm_tf32(
    const float* __restrict__ A, const float* __restrict__ W,
    const float* __restrict__ bias, float* __restrict__ C) {
    __shared__ __align__(16) float As[2][GBM][AST];
    __shared__ __align__(16) float Bs[2][GBN][AST];

    const int tid  = threadIdx.x;
    const int lane = tid & 31;
    const int wid  = tid >> 5;
    const int g    = lane >> 2;
    const int t    = lane & 3;
    const int wm   = (wid >> 1) * 32;
    const int wn   = (wid & 1) * 32;
    const int bm0  = blockIdx.y * GBM;
    const int bn0  = blockIdx.x * GBN;

    float acc[2][4][4];
#pragma unroll
    for (int i = 0; i < 2; i++)
#pragma unroll
        for (int j = 0; j < 4; j++)
#pragma unroll
            for (int k = 0; k < 4; k++) acc[i][j][k] = 0.f;

    auto load_stage = [&](int st, int kt) {
        const int kb = kt * GBK;
#pragma unroll
        for (int i = 0; i < 2; i++) {
            int c = tid + i * 256;          // 512 16B-chunks of A tile
            int row = c >> 2, cg = (c & 3) << 2;
            cpa16(&As[st][row][cg], &A[(bm0 + row) * DM + kb + cg]);
        }
        {
            int row = tid >> 2, cg = (tid & 3) << 2;  // 256 chunks of W tile
            cpa16(&Bs[st][row][cg], &W[(bn0 + row) * DM + kb + cg]);
        }
        CP_COMMIT;
    };

    load_stage(0, 0);
    const int NT = DM / GBK;  // 64
    for (int kt = 0; kt < NT; kt++) {
        if (kt + 1 < NT) {
            load_stage((kt + 1) & 1, kt + 1);
            CP_WAIT(1);
        } else {
            CP_WAIT(0);
        }
        __syncthreads();
        const int st = kt & 1;
#pragma unroll
        for (int ks = 0; ks < 2; ks++) {
            const int k0 = ks * 8;
            unsigned a[2][4];
#pragma unroll
            for (int mt = 0; mt < 2; mt++) {
                const float* r0 = &As[st][wm + mt * 16 + g][k0];
                const float* r1 = &As[st][wm + mt * 16 + g + 8][k0];
                a[mt][0] = f2tf(r0[t]);
                a[mt][1] = f2tf(r1[t]);
                a[mt][2] = f2tf(r0[t + 4]);
                a[mt][3] = f2tf(r1[t + 4]);
            }
            unsigned bb[4][2];
#pragma unroll
            for (int nt = 0; nt < 4; nt++) {
                const float* br = &Bs[st][wn + nt * 8 + g][k0];
                bb[nt][0] = f2tf(br[t]);
                bb[nt][1] = f2tf(br[t + 4]);
            }
#pragma unroll
            for (int mt = 0; mt < 2; mt++)
#pragma unroll
                for (int nt = 0; nt < 4; nt++)
                    mma8(acc[mt][nt], a[mt], bb[nt][0], bb[nt][1]);
        }
        __syncthreads();
    }

#pragma unroll
    for (int mt = 0; mt < 2; mt++) {
#pragma unroll
        for (int nt = 0; nt < 4; nt++) {
            const int r0 = bm0 + wm + mt * 16 + g;
            const int cb = bn0 + wn + nt * 8 + t * 2;
            const float b0 = bias[cb], b1 = bias[cb + 1];
            float2 v;
            v.x = acc[mt][nt][0] + b0;
            v.y = acc[mt][nt][1] + b1;
            *(float2*)&C[r0 * DM + cb] = v;
            v.x = acc[mt][nt][2] + b0;
            v.y = acc[mt][nt][3] + b1;
            *(float2*)&C[(r0 + 8) * DM + cb] = v;
        }
    }
}

// ---------------------------------------------------------------------------
// Causal flash attention, tf32 mma. One CTA = 128 q rows of one (b,h).
// K/V tiles of 64 keys. Online softmax; P staged through warp-private smem.
// Qs/Ks/Ps stride 68 (== 4 mod 32), Vs stride 72 (== 8 mod 32): fragment LDS
// patterns are conflict-free for each.
// ---------------------------------------------------------------------------
#define QST 68
#define VST 72
#define SMEM_ATTN ((128 * QST + 64 * QST + 64 * VST + 128 * QST) * 4)

__global__ __launch_bounds__(256, 2) void attn_tf32(
    const float* __restrict__ Qg, const float* __restrict__ Kg,
    const float* __restrict__ Vg, float* __restrict__ Og) {
    extern __shared__ __align__(16) float sm[];
    float* Qs = sm;                 // [128][68]
    float* Ks = Qs + 128 * QST;     // [64][68]
    float* Vs = Ks + 64 * QST;      // [64][72]
    float* Ps = Vs + 64 * VST;      // [128][68]

    const int tid  = threadIdx.x;
    const int lane = tid & 31;
    const int wid  = tid >> 5;
    const int g    = lane >> 2;
    const int t    = lane & 3;
    const int rb   = wid * 16;      // warp's 16-row band
    const int qtx  = blockIdx.x;
    const int bh   = blockIdx.y;
    const int b    = bh >> 4;
    const int h    = bh & 15;
    const int q0   = qtx * 128;

    const float* Qbase = Qg + (size_t)(b * TT) * DM + h * DK;
    const float* Kbase = Kg + (size_t)(b * TT) * DM + h * DK;
    const float* Vbase = Vg + (size_t)(b * TT) * DM + h * DK;

    // Load Q tile, pre-scaled by 1/sqrt(dk) = 0.125
#pragma unroll
    for (int i = 0; i < 8; i++) {
        int c = tid + i * 256;
        int row = c >> 4, c4 = (c & 15) << 2;
        float4 v = *(const float4*)&Qbase[(q0 + row) * DM + c4];
        v.x *= 0.125f; v.y *= 0.125f; v.z *= 0.125f; v.w *= 0.125f;
        *(float4*)&Qs[row * QST + c4] = v;
    }

    float o[8][4];
#pragma unroll
    for (int i = 0; i < 8; i++)
#pragma unroll
        for (int j = 0; j < 4; j++) o[i][j] = 0.f;
    float m0 = -1e30f, m1 = -1e30f, l0 = 0.f, l1 = 0.f;

    const int nkt = 2 * qtx + 2;  // causal: keys up to q0+127
    for (int kt = 0; kt < nkt; kt++) {
        __syncthreads();  // previous tile fully consumed
#pragma unroll
        for (int i = 0; i < 4; i++) {
            int c = tid + i * 256;
            int row = c >> 4, c4 = (c & 15) << 2;
            size_t gidx = (size_t)(kt * 64 + row) * DM + c4;
            *(float4*)&Ks[row * QST + c4] = *(const float4*)&Kbase[gidx];
            *(float4*)&Vs[row * VST + c4] = *(const float4*)&Vbase[gidx];
        }
        __syncthreads();

        // S = Q @ K^T  (16 q-rows x 64 keys per warp)
        float s[8][4];
#pragma unroll
        for (int i = 0; i < 8; i++)
#pragma unroll
            for (int j = 0; j < 4; j++) s[i][j] = 0.f;

#pragma unroll
        for (int ks = 0; ks < 8; ks++) {
            const int k0 = ks * 8;
            unsigned a[4];
            const float* q0p = &Qs[(rb + g) * QST + k0];
            const float* q1p = &Qs[(rb + g + 8) * QST + k0];
            a[0] = f2tf(q0p[t]);
            a[1] = f2tf(q1p[t]);
            a[2] = f2tf(q0p[t + 4]);
            a[3] = f2tf(q1p[t + 4]);
#pragma unroll
            for (int nt = 0; nt < 8; nt++) {
                const float* kp = &Ks[(nt * 8 + g) * QST + k0];
                mma8(s[nt], a, f2tf(kp[t]), f2tf(kp[t + 4]));
            }
        }

        const int r0g = q0 + rb + g;
        const int r1g = r0g + 8;
        if (kt >= 2 * qtx) {  // only diagonal tiles need masking
#pragma unroll
            for (int nt = 0; nt < 8; nt++) {
                int kj = kt * 64 + nt * 8 + 2 * t;
                if (kj > r0g)     s[nt][0] = -1e30f;
                if (kj + 1 > r0g) s[nt][1] = -1e30f;
                if (kj > r1g)     s[nt][2] = -1e30f;
                if (kj + 1 > r1g) s[nt][3] = -1e30f;
            }
        }

        // online softmax (rows r0g, r1g) — reductions within the lane quad
        float mt0 = -1e30f, mt1 = -1e30f;
#pragma unroll
        for (int nt = 0; nt < 8; nt++) {
            mt0 = fmaxf(mt0, fmaxf(s[nt][0], s[nt][1]));
            mt1 = fmaxf(mt1, fmaxf(s[nt][2], s[nt][3]));
        }
        mt0 = fmaxf(mt0, __shfl_xor_sync(0xffffffffu, mt0, 1));
        mt0 = fmaxf(mt0, __shfl_xor_sync(0xffffffffu, mt0, 2));
        mt1 = fmaxf(mt1, __shfl_xor_sync(0xffffffffu, mt1, 1));
        mt1 = fmaxf(mt1, __shfl_xor_sync(0xffffffffu, mt1, 2));

        const float mn0 = fmaxf(m0, mt0), mn1 = fmaxf(m1, mt1);
        const float sc0 = __expf(m0 - mn0), sc1 = __expf(m1 - mn1);
        m0 = mn0; m1 = mn1;

        float rs0 = 0.f, rs1 = 0.f;
#pragma unroll
        for (int nt = 0; nt < 8; nt++) {
            s[nt][0] = __expf(s[nt][0] - mn0);
            s[nt][1] = __expf(s[nt][1] - mn0);
            s[nt][2] = __expf(s[nt][2] - mn1);
            s[nt][3] = __expf(s[nt][3] - mn1);
            rs0 += s[nt][0] + s[nt][1];
            rs1 += s[nt][2] + s[nt][3];
        }
        rs0 += __shfl_xor_sync(0xffffffffu, rs0, 1);
        rs0 += __shfl_xor_sync(0xffffffffu, rs0, 2);
        rs1 += __shfl_xor_sync(0xffffffffu, rs1, 1);
        rs1 += __shfl_xor_sync(0xffffffffu, rs1, 2);
        l0 = l0 * sc0 + rs0;
        l1 = l1 * sc1 + rs1;

#pragma unroll
        for (int dt = 0; dt < 8; dt++) {
            o[dt][0] *= sc0; o[dt][1] *= sc0;
            o[dt][2] *= sc1; o[dt][3] *= sc1;
        }

        // stage P in warp-private smem band (D-frag -> A-frag layout fix)
#pragma unroll
        for (int nt = 0; nt < 8; nt++) {
            float2 v0; v0.x = s[nt][0]; v0.y = s[nt][1];
            *(float2*)&Ps[(rb + g) * QST + nt * 8 + 2 * t] = v0;
            float2 v1; v1.x = s[nt][2]; v1.y = s[nt][3];
            *(float2*)&Ps[(rb + g + 8) * QST + nt * 8 + 2 * t] = v1;
        }
        __syncwarp();

        // O += P @ V
#pragma unroll
        for (int ks = 0; ks < 8; ks++) {
            const int k0 = ks * 8;
            unsigned a[4];
            const float* p0 = &Ps[(rb + g) * QST + k0];
            const float* p1 = &Ps[(rb + g + 8) * QST + k0];
            a[0] = f2tf(p0[t]);
            a[1] = f2tf(p1[t]);
            a[2] = f2tf(p0[t + 4]);
            a[3] = f2tf(p1[t + 4]);
#pragma unroll
            for (int dt = 0; dt < 8; dt++) {
                unsigned b0 = f2tf(Vs[(k0 + t) * VST + dt * 8 + g]);
                unsigned b1 = f2tf(Vs[(k0 + t + 4) * VST + dt * 8 + g]);
                mma8(o[dt], a, b0, b1);
            }
        }
    }

    const float i0 = 1.f / l0, i1 = 1.f / l1;
    const int r0g = q0 + rb + g;
    float* Ob = Og + (size_t)(b * TT + r0g) * DM + h * DK;
#pragma unroll
    for (int dt = 0; dt < 8; dt++) {
        const int col = dt * 8 + 2 * t;
        float2 v;
        v.x = o[dt][0] * i0; v.y = o[dt][1] * i0;
        *(float2*)&Ob[col] = v;
        v.x = o[dt][2] * i1; v.y = o[dt][3] * i1;
        *(float2*)&Ob[8 * DM + col] = v;
    }
}

// ---------------------------------------------------------------------------
// launch: 3 projection GEMMs -> attention -> output GEMM (5 graph nodes)
// input order: q, mask, Wq, bq, Wk, bk, Wv, bv, Wo, bo (mask ignored: causal)
// ---------------------------------------------------------------------------
extern "C" void kernel_launch(void* const* d_in, const int* in_sizes, int n_in,
                              void* d_out, int out_size) {
    (void)in_sizes; (void)n_in; (void)out_size;
    const float* q  = (const float*)d_in[0];
    const float* Wq = (const float*)d_in[2];
    const float* bq = (const float*)d_in[3];
    const float* Wk = (const float*)d_in[4];
    const float* bk = (const float*)d_in[5];
    const float* Wv = (const float*)d_in[6];
    const float* bv = (const float*)d_in[7];
    const float* Wo = (const float*)d_in[8];
    const float* bo = (const float*)d_in[9];
    float* out = (float*)d_out;

    float *pQ, *pK, *pV, *pA;
    cudaGetSymbolAddress((void**)&pQ, g_Q);
    cudaGetSymbolAddress((void**)&pK, g_K);
    cudaGetSymbolAddress((void**)&pV, g_V);
    cudaGetSymbolAddress((void**)&pA, g_A);

    cudaFuncSetAttribute(attn_tf32, cudaFuncAttributeMaxDynamicSharedMemorySize,
                         SMEM_ATTN);

    dim3 gg(DM / GBN, (NB * TT) / GBM);  // (16, 64)
    gemm_tf32<<<gg, 256>>>(q, Wq, bq, pQ);
    gemm_tf32<<<gg, 256>>>(q, Wk, bk, pK);
    gemm_tf32<<<gg, 256>>>(q, Wv, bv, pV);
    attn_tf32<<<dim3(TT / 128, NB * NH), 256, SMEM_ATTN>>>(pQ, pK, pV, pA);
    gemm_tf32<<<gg, 256>>>(pA, Wo, bo, out);
}

// round 5
// speedup vs baseline: 1.0278x; 1.0278x over previous
#include <cuda_runtime.h>

// Problem constants
#define DM 1024
#define TT 2048
#define NB 4
#define NH 16
#define DK 64

// Scratch (__device__ globals: no allocation allowed anywhere)
__device__ float g_Q[NB * TT * DM];
__device__ float g_K[NB * TT * DM];
__device__ float g_V[NB * TT * DM];
__device__ float g_A[NB * TT * DM];
__device__ float g_Qr[NB * TT * DM];   // tf32-rounded input activations
__device__ float g_Wr[4 * DM * DM];    // tf32-rounded Wq,Wk,Wv,Wo

// ---------------------------------------------------------------------------
// helpers
// ---------------------------------------------------------------------------
__device__ __forceinline__ unsigned f2tf(float x) {
    unsigned u;
    asm("cvt.rna.tf32.f32 %0, %1;" : "=r"(u) : "f"(x));
    return u;
}
__device__ __forceinline__ float f2tff(float x) { return __uint_as_float(f2tf(x)); }

__device__ __forceinline__ void mma8(float (&d)[4], const unsigned (&a)[4],
                                     unsigned b0, unsigned b1) {
    asm volatile(
        "mma.sync.aligned.m16n8k8.row.col.f32.tf32.tf32.f32 "
        "{%0,%1,%2,%3}, {%4,%5,%6,%7}, {%8,%9}, {%0,%1,%2,%3};"
        : "+f"(d[0]), "+f"(d[1]), "+f"(d[2]), "+f"(d[3])
        : "r"(a[0]), "r"(a[1]), "r"(a[2]), "r"(a[3]), "r"(b0), "r"(b1));
}

__device__ __forceinline__ void cpa16(void* s, const void* g) {
    unsigned sa = (unsigned)__cvta_generic_to_shared(s);
    asm volatile("cp.async.cg.shared.global [%0], [%1], 16;" ::"r"(sa), "l"(g));
}
#define CP_COMMIT asm volatile("cp.async.commit_group;")
#define CP_WAIT(n) asm volatile("cp.async.wait_group %0;" ::"n"(n))

// ---------------------------------------------------------------------------
// Elementwise pre-round fp32 -> tf32(RNA) stored as fp32 (low 13 bits zero).
// Lets GEMMs feed raw bits to mma.sync with no inner-loop CVT.
// ---------------------------------------------------------------------------
__global__ void round_tf32(const float* __restrict__ s, float* __restrict__ d) {
    int i = (blockIdx.x * 256 + threadIdx.x) * 4;
    float4 v = *(const float4*)&s[i];
    v.x = f2tff(v.x); v.y = f2tff(v.y); v.z = f2tff(v.z); v.w = f2tff(v.w);
    *(float4*)&d[i] = v;
}

// ---------------------------------------------------------------------------
// GEMM: C[8192,1024] = A @ W^T + bias. A,W pre-rounded to tf32.
// Block 128x128, BK=16, 4-stage cp.async, 256 threads, warp tile 32x64.
// Smem row stride 20 floats (20 mod 32 -> conflict-free fragment LDS).
// ---------------------------------------------------------------------------
#define GBM 128
#define GBN 128
#define GBK 16
#define GST 20
#define NSTG 4
#define GSTAGE ((GBM + GBN) * GST)
#define SMEM_GEMM (NSTG * GSTAGE * 4)

__global__ __launch_bounds__(256, 2) void gemm_tf32(
    const float* __restrict__ A, const float* __restrict__ W,
    const float* __restrict__ bias, float* __restrict__ C) {
    extern __shared__ float sg[];

    const int tid  = threadIdx.x;
    const int lane = tid & 31;
    const int wid  = tid >> 5;
    const int g    = lane >> 2;
    const int t    = lane & 3;
    const int wm   = (wid >> 1) * 32;
    const int wn   = (wid & 1) * 64;
    const int bm0  = blockIdx.y * GBM;
    const int bn0  = blockIdx.x * GBN;
    const int ar   = tid >> 2;          // 0..63
    const int ac   = (tid & 3) << 2;    // 0,4,8,12

    float acc[2][8][4];
#pragma unroll
    for (int i = 0; i < 2; i++)
#pragma unroll
        for (int j = 0; j < 8; j++)
#pragma unroll
            for (int k = 0; k < 4; k++) acc[i][j][k] = 0.f;

    auto load_stage = [&](int st, int kt) {
        float* As = sg + st * GSTAGE;
        float* Bs = As + GBM * GST;
        const int kb = kt * GBK;
        cpa16(&As[ar * GST + ac],        &A[(bm0 + ar) * DM + kb + ac]);
        cpa16(&As[(ar + 64) * GST + ac], &A[(bm0 + ar + 64) * DM + kb + ac]);
        cpa16(&Bs[ar * GST + ac],        &W[(bn0 + ar) * DM + kb + ac]);
        cpa16(&Bs[(ar + 64) * GST + ac], &W[(bn0 + ar + 64) * DM + kb + ac]);
        CP_COMMIT;
    };

    load_stage(0, 0);
    load_stage(1, 1);
    load_stage(2, 2);

    const int NT = DM / GBK;  // 64
    for (int kt = 0; kt < NT; kt++) {
        CP_WAIT(2);
        __syncthreads();
        if (kt + 3 < NT) load_stage((kt + 3) & 3, kt + 3);

        const float* As = sg + (kt & 3) * GSTAGE;
        const float* Bs = As + GBM * GST;
#pragma unroll
        for (int ks = 0; ks < 2; ks++) {
            const int k0 = ks * 8;
            unsigned a[2][4];
#pragma unroll
            for (int mt = 0; mt < 2; mt++) {
                const unsigned* r0 = (const unsigned*)&As[(wm + mt * 16 + g) * GST + k0];
                const unsigned* r1 = (const unsigned*)&As[(wm + mt * 16 + g + 8) * GST + k0];
                a[mt][0] = r0[t];
                a[mt][1] = r1[t];
                a[mt][2] = r0[t + 4];
                a[mt][3] = r1[t + 4];
            }
            unsigned bb[8][2];
#pragma unroll
            for (int nt = 0; nt < 8; nt++) {
                const unsigned* br = (const unsigned*)&Bs[(wn + nt * 8 + g) * GST + k0];
                bb[nt][0] = br[t];
                bb[nt][1] = br[t + 4];
            }
#pragma unroll
            for (int mt = 0; mt < 2; mt++)
#pragma unroll
                for (int nt = 0; nt < 8; nt++)
                    mma8(acc[mt][nt], a[mt], bb[nt][0], bb[nt][1]);
        }
    }

#pragma unroll
    for (int mt = 0; mt < 2; mt++) {
#pragma unroll
        for (int nt = 0; nt < 8; nt++) {
            const int r0 = bm0 + wm + mt * 16 + g;
            const int cb = bn0 + wn + nt * 8 + t * 2;
            const float b0 = bias[cb], b1 = bias[cb + 1];
            float2 v;
            v.x = acc[mt][nt][0] + b0;
            v.y = acc[mt][nt][1] + b1;
            *(float2*)&C[r0 * DM + cb] = v;
            v.x = acc[mt][nt][2] + b0;
            v.y = acc[mt][nt][3] + b1;
            *(float2*)&C[(r0 + 8) * DM + cb] = v;
        }
    }
}

// ---------------------------------------------------------------------------
// Causal flash attention, tf32 mma. One CTA = 128 q rows of one (b,h).
// K/V tiles of 64 keys, double-buffered in smem with register prefetch
// (8 LDG.128/thread in flight during compute). All smem operands stored
// PRE-CONVERTED to tf32 -> inner loops are pure LDS + HMMA, zero CVT.
// Strides: QST=68 (==4 mod 32), VST=72 (==8 mod 32): conflict-free LDS.
// q-tile order reversed so heavy causal tiles launch first.
// ---------------------------------------------------------------------------
#define QST 68
#define VST 72
#define AK (128 * QST)
#define AV (AK + 2 * 64 * QST)
#define AP (AV + 2 * 64 * VST)
#define SMEM_ATTN ((AP + 128 * QST) * 4)

__global__ __launch_bounds__(256) void attn_tf32(
    const float* __restrict__ Qg, const float* __restrict__ Kg,
    const float* __restrict__ Vg, float* __restrict__ Og) {
    extern __shared__ unsigned su[];
    unsigned* Qs = su;              // [128][QST] tf32
    unsigned* Ks = su + AK;         // [2][64][QST]
    unsigned* Vs = su + AV;         // [2][64][VST]
    unsigned* Ps = su + AP;         // [128][QST]

    const int tid  = threadIdx.x;
    const int lane = tid & 31;
    const int wid  = tid >> 5;
    const int g    = lane >> 2;
    const int t    = lane & 3;
    const int rb   = wid * 16;
    const int qtx  = gridDim.x - 1 - blockIdx.x;   // heavy tiles first
    const int bh   = blockIdx.y;
    const int b    = bh >> 4;
    const int h    = bh & 15;
    const int q0   = qtx * 128;

    const float* Qbase = Qg + (size_t)(b * TT) * DM + h * DK;
    const float* Kbase = Kg + (size_t)(b * TT) * DM + h * DK;
    const float* Vbase = Vg + (size_t)(b * TT) * DM + h * DK;

    // Q tile: load, scale by 1/sqrt(dk)=0.125, convert, store tf32
#pragma unroll
    for (int i = 0; i < 8; i++) {
        int c = tid + i * 256;
        int row = c >> 4, c4 = (c & 15) << 2;
        float4 v = *(const float4*)&Qbase[(q0 + row) * DM + c4];
        uint4 u;
        u.x = f2tf(v.x * 0.125f);
        u.y = f2tf(v.y * 0.125f);
        u.z = f2tf(v.z * 0.125f);
        u.w = f2tf(v.w * 0.125f);
        *(uint4*)&Qs[row * QST + c4] = u;
    }

    float4 kb4[4], vb4[4];  // register prefetch buffer: one 64-key K+V tile
    auto ldKV = [&](int kt) {
#pragma unroll
        for (int i = 0; i < 4; i++) {
            int c = tid + i * 256;
            int row = c >> 4, c4 = (c & 15) << 2;
            size_t gi = (size_t)(kt * 64 + row) * DM + c4;
            kb4[i] = *(const float4*)&Kbase[gi];
            vb4[i] = *(const float4*)&Vbase[gi];
        }
    };
    auto stKV = [&](int st) {
        unsigned* Kd = Ks + st * 64 * QST;
        unsigned* Vd = Vs + st * 64 * VST;
#pragma unroll
        for (int i = 0; i < 4; i++) {
            int c = tid + i * 256;
            int row = c >> 4, c4 = (c & 15) << 2;
            uint4 u;
            u.x = f2tf(kb4[i].x); u.y = f2tf(kb4[i].y);
            u.z = f2tf(kb4[i].z); u.w = f2tf(kb4[i].w);
            *(uint4*)&Kd[row * QST + c4] = u;
            uint4 w;
            w.x = f2tf(vb4[i].x); w.y = f2tf(vb4[i].y);
            w.z = f2tf(vb4[i].z); w.w = f2tf(vb4[i].w);
            *(uint4*)&Vd[row * VST + c4] = w;
        }
    };

    const int nkt = 2 * qtx + 2;  // causal
    ldKV(0);
    stKV(0);
    if (nkt > 1) ldKV(1);
    __syncthreads();

    float o[8][4];
#pragma unroll
    for (int i = 0; i < 8; i++)
#pragma unroll
        for (int j = 0; j < 4; j++) o[i][j] = 0.f;
    float m0 = -1e30f, m1 = -1e30f, l0 = 0.f, l1 = 0.f;

    for (int kt = 0; kt < nkt; kt++) {
        // drain prefetch regs into the other smem stage, start next LDG burst
        if (kt + 1 < nkt) {
            stKV((kt + 1) & 1);
            if (kt + 2 < nkt) ldKV(kt + 2);
        }
        const unsigned* Kst = Ks + (kt & 1) * 64 * QST;
        const unsigned* Vst = Vs + (kt & 1) * 64 * VST;

        // S = Q @ K^T (16 q-rows x 64 keys per warp), pure LDS+HMMA
        float s[8][4];
#pragma unroll
        for (int i = 0; i < 8; i++)
#pragma unroll
            for (int j = 0; j < 4; j++) s[i][j] = 0.f;

#pragma unroll
        for (int ks = 0; ks < 8; ks++) {
            const int k0 = ks * 8;
            unsigned a[4];
            const unsigned* q0p = &Qs[(rb + g) * QST + k0];
            const unsigned* q1p = &Qs[(rb + g + 8) * QST + k0];
            a[0] = q0p[t];
            a[1] = q1p[t];
            a[2] = q0p[t + 4];
            a[3] = q1p[t + 4];
#pragma unroll
            for (int nt = 0; nt < 8; nt++) {
                const unsigned* kp = &Kst[(nt * 8 + g) * QST + k0];
                mma8(s[nt], a, kp[t], kp[t + 4]);
            }
        }

        const int r0g = q0 + rb + g;
        const int r1g = r0g + 8;
        if (kt >= 2 * qtx) {  // only the 2 diagonal tiles mask
#pragma unroll
            for (int nt = 0; nt < 8; nt++) {
                int kj = kt * 64 + nt * 8 + 2 * t;
                if (kj > r0g)     s[nt][0] = -1e30f;
                if (kj + 1 > r0g) s[nt][1] = -1e30f;
                if (kj > r1g)     s[nt][2] = -1e30f;
                if (kj + 1 > r1g) s[nt][3] = -1e30f;
            }
        }

        // online softmax (rows r0g, r1g); reductions within the lane quad
        float mt0 = -1e30f, mt1 = -1e30f;
#pragma unroll
        for (int nt = 0; nt < 8; nt++) {
            mt0 = fmaxf(mt0, fmaxf(s[nt][0], s[nt][1]));
            mt1 = fmaxf(mt1, fmaxf(s[nt][2], s[nt][3]));
        }
        mt0 = fmaxf(mt0, __shfl_xor_sync(0xffffffffu, mt0, 1));
        mt0 = fmaxf(mt0, __shfl_xor_sync(0xffffffffu, mt0, 2));
        mt1 = fmaxf(mt1, __shfl_xor_sync(0xffffffffu, mt1, 1));
        mt1 = fmaxf(mt1, __shfl_xor_sync(0xffffffffu, mt1, 2));

        const float mn0 = fmaxf(m0, mt0), mn1 = fmaxf(m1, mt1);
        const float sc0 = __expf(m0 - mn0), sc1 = __expf(m1 - mn1);
        m0 = mn0; m1 = mn1;

        float rs0 = 0.f, rs1 = 0.f;
#pragma unroll
        for (int nt = 0; nt < 8; nt++) {
            s[nt][0] = __expf(s[nt][0] - mn0);
            s[nt][1] = __expf(s[nt][1] - mn0);
            s[nt][2] = __expf(s[nt][2] - mn1);
            s[nt][3] = __expf(s[nt][3] - mn1);
            rs0 += s[nt][0] + s[nt][1];
            rs1 += s[nt][2] + s[nt][3];
        }
        rs0 += __shfl_xor_sync(0xffffffffu, rs0, 1);
        rs0 += __shfl_xor_sync(0xffffffffu, rs0, 2);
        rs1 += __shfl_xor_sync(0xffffffffu, rs1, 1);
        rs1 += __shfl_xor_sync(0xffffffffu, rs1, 2);
        l0 = l0 * sc0 + rs0;
        l1 = l1 * sc1 + rs1;

#pragma unroll
        for (int dt = 0; dt < 8; dt++) {
            o[dt][0] *= sc0; o[dt][1] *= sc0;
            o[dt][2] *= sc1; o[dt][3] *= sc1;
        }

        // stage P (tf32) in warp-private smem band for A-fragment layout
#pragma unroll
        for (int nt = 0; nt < 8; nt++) {
            uint2 v0; v0.x = f2tf(s[nt][0]); v0.y = f2tf(s[nt][1]);
            *(uint2*)&Ps[(rb + g) * QST + nt * 8 + 2 * t] = v0;
            uint2 v1; v1.x = f2tf(s[nt][2]); v1.y = f2tf(s[nt][3]);
            *(uint2*)&Ps[(rb + g + 8) * QST + nt * 8 + 2 * t] = v1;
        }
        __syncwarp();

        // O += P @ V
#pragma unroll
        for (int ks = 0; ks < 8; ks++) {
            const int k0 = ks * 8;
            unsigned a[4];
            const unsigned* p0 = &Ps[(rb + g) * QST + k0];
            const unsigned* p1 = &Ps[(rb + g + 8) * QST + k0];
            a[0] = p0[t];
            a[1] = p1[t];
            a[2] = p0[t + 4];
            a[3] = p1[t + 4];
#pragma unroll
            for (int dt = 0; dt < 8; dt++) {
                unsigned b0 = Vst[(k0 + t) * VST + dt * 8 + g];
                unsigned b1 = Vst[(k0 + t + 4) * VST + dt * 8 + g];
                mma8(o[dt], a, b0, b1);
            }
        }
        __syncthreads();  // stage fully consumed; next iter may overwrite
    }

    // epilogue: normalize and store tf32-ROUNDED (feeds final GEMM raw)
    const float i0 = 1.f / l0, i1 = 1.f / l1;
    const int r0g = q0 + rb + g;
    float* Ob = Og + (size_t)(b * TT + r0g) * DM + h * DK;
#pragma unroll
    for (int dt = 0; dt < 8; dt++) {
        const int col = dt * 8 + 2 * t;
        float2 v;
        v.x = f2tff(o[dt][0] * i0); v.y = f2tff(o[dt][1] * i0);
        *(float2*)&Ob[col] = v;
        v.x = f2tff(o[dt][2] * i1); v.y = f2tff(o[dt][3] * i1);
        *(float2*)&Ob[8 * DM + col] = v;
    }
}

// ---------------------------------------------------------------------------
// launch: 5 round kernels -> 3 projection GEMMs -> attention -> output GEMM
// input order: q, mask, Wq, bq, Wk, bk, Wv, bv, Wo, bo (mask ignored: causal)
// ---------------------------------------------------------------------------
extern "C" void kernel_launch(void* const* d_in, const int* in_sizes, int n_in,
                              void* d_out, int out_size) {
    (void)in_sizes; (void)n_in; (void)out_size;
    const float* q  = (const float*)d_in[0];
    const float* Wq = (const float*)d_in[2];
    const float* bq = (const float*)d_in[3];
    const float* Wk = (const float*)d_in[4];
    const float* bk = (const float*)d_in[5];
    const float* Wv = (const float*)d_in[6];
    const float* bv = (const float*)d_in[7];
    const float* Wo = (const float*)d_in[8];
    const float* bo = (const float*)d_in[9];
    float* out = (float*)d_out;

    float *pQ, *pK, *pV, *pA, *pQr, *pW;
    cudaGetSymbolAddress((void**)&pQ, g_Q);
    cudaGetSymbolAddress((void**)&pK, g_K);
    cudaGetSymbolAddress((void**)&pV, g_V);
    cudaGetSymbolAddress((void**)&pA, g_A);
    cudaGetSymbolAddress((void**)&pQr, g_Qr);
    cudaGetSymbolAddress((void**)&pW, g_Wr);

    cudaFuncSetAttribute(gemm_tf32, cudaFuncAttributeMaxDynamicSharedMemorySize,
                         SMEM_GEMM);
    cudaFuncSetAttribute(attn_tf32, cudaFuncAttributeMaxDynamicSharedMemorySize,
                         SMEM_ATTN);

    // pre-round activations + weights to tf32
    round_tf32<<<(NB * TT * DM) / 1024, 256>>>(q, pQr);
    round_tf32<<<(DM * DM) / 1024, 256>>>(Wq, pW + 0 * DM * DM);
    round_tf32<<<(DM * DM) / 1024, 256>>>(Wk, pW + 1 * DM * DM);
    round_tf32<<<(DM * DM) / 1024, 256>>>(Wv, pW + 2 * DM * DM);
    round_tf32<<<(DM * DM) / 1024, 256>>>(Wo, pW + 3 * DM * DM);

    dim3 gg(DM / GBN, (NB * TT) / GBM);  // (8, 64)
    gemm_tf32<<<gg, 256, SMEM_GEMM>>>(pQr, pW + 0 * DM * DM, bq, pQ);
    gemm_tf32<<<gg, 256, SMEM_GEMM>>>(pQr, pW + 1 * DM * DM, bk, pK);
    gemm_tf32<<<gg, 256, SMEM_GEMM>>>(pQr, pW + 2 * DM * DM, bv, pV);

    attn_tf32<<<dim3(TT / 128, NB * NH), 256, SMEM_ATTN>>>(pQ, pK, pV, pA);

    gemm_tf32<<<gg, 256, SMEM_GEMM>>>(pA, pW + 3 * DM * DM, bo, out);
}

// round 6
// speedup vs baseline: 2.3923x; 2.3275x over previous
#include <cuda_runtime.h>
#include <cuda_fp16.h>

#define DM 1024
#define TT 2048
#define NB 4
#define NH 16
#define DK 64

// Scratch (__device__ globals; allocation is forbidden everywhere)
__device__ __half g_Xh[NB * TT * DM];          // fp16 input activations
__device__ __half g_W4[4 * DM * DM];           // fp16 Wq,Wk,Wv,Wo (concat)
__device__ float  g_b3[3 * DM];                // concat bq,bk,bv
__device__ __half g_QKV[NB * TT * 3 * DM];     // fused projection output
__device__ __half g_AO[NB * TT * DM];          // attention output (fp16)

// ---------------------------------------------------------------------------
// helpers
// ---------------------------------------------------------------------------
__device__ __forceinline__ unsigned h2pack(float lo, float hi) {
    unsigned u;
    asm("cvt.rn.f16x2.f32 %0, %1, %2;" : "=r"(u) : "f"(hi), "f"(lo));
    return u;
}

__device__ __forceinline__ void mma16(float (&d)[4], const unsigned (&a)[4],
                                      unsigned b0, unsigned b1) {
    asm volatile(
        "mma.sync.aligned.m16n8k16.row.col.f32.f16.f16.f32 "
        "{%0,%1,%2,%3}, {%4,%5,%6,%7}, {%8,%9}, {%0,%1,%2,%3};"
        : "+f"(d[0]), "+f"(d[1]), "+f"(d[2]), "+f"(d[3])
        : "r"(a[0]), "r"(a[1]), "r"(a[2]), "r"(a[3]), "r"(b0), "r"(b1));
}

__device__ __forceinline__ void ldsm4(unsigned (&r)[4], unsigned addr) {
    asm volatile("ldmatrix.sync.aligned.m8n8.x4.shared.b16 {%0,%1,%2,%3}, [%4];"
                 : "=r"(r[0]), "=r"(r[1]), "=r"(r[2]), "=r"(r[3]) : "r"(addr));
}
__device__ __forceinline__ void ldsm4t(unsigned (&r)[4], unsigned addr) {
    asm volatile("ldmatrix.sync.aligned.m8n8.x4.trans.shared.b16 {%0,%1,%2,%3}, [%4];"
                 : "=r"(r[0]), "=r"(r[1]), "=r"(r[2]), "=r"(r[3]) : "r"(addr));
}

__device__ __forceinline__ void cpa16(unsigned sa, const void* g) {
    asm volatile("cp.async.cg.shared.global [%0], [%1], 16;" ::"r"(sa), "l"(g));
}
#define CP_COMMIT asm volatile("cp.async.commit_group;")
#define CP_WAIT(n) asm volatile("cp.async.wait_group %0;" ::"n"(n))

// ---------------------------------------------------------------------------
// elementwise fp32 -> fp16 (4 elts/thread)
// ---------------------------------------------------------------------------
__global__ void f2h4(const float* __restrict__ s, __half* __restrict__ d) {
    int i = (blockIdx.x * 256 + threadIdx.x) * 4;
    float4 v = *(const float4*)&s[i];
    uint2 u;
    u.x = h2pack(v.x, v.y);
    u.y = h2pack(v.z, v.w);
    *(uint2*)&d[i] = u;
}

__global__ void bias_cat(const float* __restrict__ bq, const float* __restrict__ bk,
                         const float* __restrict__ bv, float* __restrict__ d) {
    int i = blockIdx.x * 256 + threadIdx.x;  // 0..3071
    const float* s = (i < DM) ? bq : (i < 2 * DM) ? bk : bv;
    d[i] = s[i & (DM - 1)];
}

// ---------------------------------------------------------------------------
// fp16 GEMM: C[M,N] = A[M,1024] @ W[N,1024]^T + bias
// Block 128x128, BK=32, 4-stage cp.async, 256 threads, warp tile 32x64.
// Smem row stride 40 halves (80B): 8-row ldmatrix groups hit distinct 16B
// banks -> conflict-free. QKV=1: fp16 out, row stride 3072, Q-cols scaled.
// ---------------------------------------------------------------------------
#define GBM 128
#define GBN 128
#define GBK 32
#define GST 40
#define GSTG ((GBM + GBN) * GST)      // halves per stage (10240)
#define SMEM_GEMM (4 * GSTG * 2)      // 81920 B

template <int QKV>
__global__ __launch_bounds__(256, 2) void gemm_f16(
    const __half* __restrict__ A, const __half* __restrict__ W,
    const float* __restrict__ bias, void* __restrict__ Cv) {
    extern __shared__ __half sh[];
    const unsigned sbase = (unsigned)__cvta_generic_to_shared(sh);

    const int tid  = threadIdx.x;
    const int lane = tid & 31;
    const int wid  = tid >> 5;
    const int g    = lane >> 2;
    const int t    = lane & 3;
    const int wm   = (wid >> 1) * 32;
    const int wn   = (wid & 1) * 64;
    const int bm0  = blockIdx.y * GBM;
    const int bn0  = blockIdx.x * GBN;
    const int OST  = QKV ? 3 * DM : DM;

    float acc[2][8][4];
#pragma unroll
    for (int i = 0; i < 2; i++)
#pragma unroll
        for (int j = 0; j < 8; j++)
#pragma unroll
            for (int k = 0; k < 4; k++) acc[i][j][k] = 0.f;

    auto load_stage = [&](int st, int kt) {
        unsigned as = sbase + st * GSTG * 2;
        unsigned bs = as + GBM * GST * 2;
        const int kb = kt * GBK;
#pragma unroll
        for (int i = 0; i < 2; i++) {
            int c = tid + i * 256;               // 512 A-chunks of 16B
            int r = c >> 2, kc = (c & 3) * 8;
            cpa16(as + (r * GST + kc) * 2, &A[(size_t)(bm0 + r) * DM + kb + kc]);
        }
#pragma unroll
        for (int i = 0; i < 2; i++) {
            int c = tid + i * 256;               // 512 W-chunks
            int r = c >> 2, kc = (c & 3) * 8;
            cpa16(bs + (r * GST + kc) * 2, &W[(size_t)(bn0 + r) * DM + kb + kc]);
        }
        CP_COMMIT;
    };

    // ldmatrix lane geometry
    const int arow  = (lane & 7) + ((lane >> 3) & 1) * 8;
    const int akoff = (lane >> 4) * 8;
    const int brow  = ((lane >> 4) & 1) * 8 + (lane & 7);
    const int bkoff = ((lane >> 3) & 1) * 8;

    load_stage(0, 0);
    load_stage(1, 1);
    load_stage(2, 2);

    const int NT = DM / GBK;  // 32
    for (int kt = 0; kt < NT; kt++) {
        if (kt + 2 < NT)      CP_WAIT(2);
        else if (kt + 1 < NT) CP_WAIT(1);
        else                  CP_WAIT(0);
        __syncthreads();
        if (kt + 3 < NT) load_stage((kt + 3) & 3, kt + 3);

        unsigned as = sbase + (kt & 3) * GSTG * 2;
        unsigned bs = as + GBM * GST * 2;
#pragma unroll
        for (int ks = 0; ks < 2; ks++) {
            const int k0 = ks * 16;
            unsigned a[2][4];
#pragma unroll
            for (int mt = 0; mt < 2; mt++)
                ldsm4(a[mt], as + ((wm + mt * 16 + arow) * GST + k0 + akoff) * 2);
#pragma unroll
            for (int j = 0; j < 4; j++) {
                unsigned bf[4];
                ldsm4(bf, bs + ((wn + j * 16 + brow) * GST + k0 + bkoff) * 2);
#pragma unroll
                for (int mt = 0; mt < 2; mt++) {
                    mma16(acc[mt][2 * j],     a[mt], bf[0], bf[1]);
                    mma16(acc[mt][2 * j + 1], a[mt], bf[2], bf[3]);
                }
            }
        }
    }

#pragma unroll
    for (int mt = 0; mt < 2; mt++) {
#pragma unroll
        for (int nt = 0; nt < 8; nt++) {
            const int r0 = bm0 + wm + mt * 16 + g;
            const int cb = bn0 + wn + nt * 8 + 2 * t;
            const float b0 = bias[cb], b1 = bias[cb + 1];
            if (QKV) {
                const float sc = (cb < DM) ? 0.125f : 1.f;  // fold 1/sqrt(dk) into Q
                __half* C = (__half*)Cv;
                *(unsigned*)&C[(size_t)r0 * OST + cb] =
                    h2pack((acc[mt][nt][0] + b0) * sc, (acc[mt][nt][1] + b1) * sc);
                *(unsigned*)&C[(size_t)(r0 + 8) * OST + cb] =
                    h2pack((acc[mt][nt][2] + b0) * sc, (acc[mt][nt][3] + b1) * sc);
            } else {
                float* C = (float*)Cv;
                float2 v;
                v.x = acc[mt][nt][0] + b0;
                v.y = acc[mt][nt][1] + b1;
                *(float2*)&C[(size_t)r0 * OST + cb] = v;
                v.x = acc[mt][nt][2] + b0;
                v.y = acc[mt][nt][3] + b1;
                *(float2*)&C[(size_t)(r0 + 8) * OST + cb] = v;
            }
        }
    }
}

// ---------------------------------------------------------------------------
// Causal flash attention, fp16 m16n8k16. One CTA = 128 q rows of one (b,h).
// 64-key K/V tiles, 3-stage cp.async ring. Q/K frags via ldmatrix, V via
// ldmatrix.trans, P register-direct (D-frag == A-frag layout for k16).
// Smem row stride 72 halves (144B): conflict-free ldmatrix.
// ---------------------------------------------------------------------------
#define AST 72
#define AK_OFF (128 * AST)
#define AV_OFF (AK_OFF + 3 * 64 * AST)
#define SMEM_ATTN ((AV_OFF + 3 * 64 * AST) * 2)   // 73728 B

__global__ __launch_bounds__(256) void attn_f16(
    const __half* __restrict__ QKV, __half* __restrict__ AO) {
    extern __shared__ __half sh[];
    const unsigned sbase = (unsigned)__cvta_generic_to_shared(sh);

    const int tid  = threadIdx.x;
    const int lane = tid & 31;
    const int wid  = tid >> 5;
    const int g    = lane >> 2;
    const int t    = lane & 3;
    const int rb   = wid * 16;
    const int qtx  = gridDim.x - 1 - blockIdx.x;  // heavy causal tiles first
    const int bh   = blockIdx.y;
    const int b    = bh >> 4;
    const int h    = bh & 15;
    const int q0   = qtx * 128;

    const __half* Qb = QKV + (size_t)(b * TT) * 3 * DM + h * DK;
    const __half* Kb = Qb + DM;
    const __half* Vb = Qb + 2 * DM;

    auto ldKV = [&](int kt, int st) {
#pragma unroll
        for (int i = 0; i < 2; i++) {
            int c = tid + i * 256;
            int r = c >> 3, kc = (c & 7) * 8;
            size_t gro = (size_t)(kt * 64 + r) * 3 * DM + kc;
            cpa16(sbase + (AK_OFF + st * 64 * AST + r * AST + kc) * 2, Kb + gro);
            cpa16(sbase + (AV_OFF + st * 64 * AST + r * AST + kc) * 2, Vb + gro);
        }
    };

    const int nkt = 2 * qtx + 2;  // causal tile count
    {  // Q tile + KV tile 0 -> group 0; KV tile 1 -> group 1
#pragma unroll
        for (int i = 0; i < 4; i++) {
            int c = tid + i * 256;
            int r = c >> 3, kc = (c & 7) * 8;
            cpa16(sbase + (r * AST + kc) * 2, Qb + (size_t)(q0 + r) * 3 * DM + kc);
        }
        ldKV(0, 0);
        CP_COMMIT;
        ldKV(1, 1);
        CP_COMMIT;
    }

    float o[8][4];
#pragma unroll
    for (int i = 0; i < 8; i++)
#pragma unroll
        for (int j = 0; j < 4; j++) o[i][j] = 0.f;
    float m0 = -1e30f, m1 = -1e30f, l0 = 0.f, l1 = 0.f;

    const int arow  = (lane & 7) + ((lane >> 3) & 1) * 8;
    const int akoff = (lane >> 4) * 8;
    const int brow  = ((lane >> 4) & 1) * 8 + (lane & 7);
    const int bkoff = ((lane >> 3) & 1) * 8;
    const int vrow  = (lane & 7) + ((lane >> 3) & 1) * 8;
    const int vcol  = ((lane >> 4) & 1) * 8;

    for (int kt = 0; kt < nkt; kt++) {
        if (kt + 1 < nkt) CP_WAIT(1);
        else              CP_WAIT(0);
        __syncthreads();
        if (kt + 2 < nkt) { ldKV(kt + 2, (kt + 2) % 3); CP_COMMIT; }

        const unsigned Kst = sbase + (AK_OFF + (kt % 3) * 64 * AST) * 2;
        const unsigned Vst = sbase + (AV_OFF + (kt % 3) * 64 * AST) * 2;

        // S = Q @ K^T : 16 q-rows x 64 keys per warp
        float s[8][4];
#pragma unroll
        for (int i = 0; i < 8; i++)
#pragma unroll
            for (int j = 0; j < 4; j++) s[i][j] = 0.f;

#pragma unroll
        for (int ks = 0; ks < 4; ks++) {
            const int k0 = ks * 16;
            unsigned a[4];
            ldsm4(a, sbase + ((rb + arow) * AST + k0 + akoff) * 2);
#pragma unroll
            for (int j = 0; j < 4; j++) {
                unsigned bf[4];
                ldsm4(bf, Kst + ((j * 16 + brow) * AST + k0 + bkoff) * 2);
                mma16(s[2 * j],     a, bf[0], bf[1]);
                mma16(s[2 * j + 1], a, bf[2], bf[3]);
            }
        }

        const int r0g = q0 + rb + g;
        const int r1g = r0g + 8;
        if (kt >= 2 * qtx) {  // only the 2 diagonal tiles mask
#pragma unroll
            for (int nt = 0; nt < 8; nt++) {
                int kj = kt * 64 + nt * 8 + 2 * t;
                if (kj > r0g)     s[nt][0] = -1e30f;
                if (kj + 1 > r0g) s[nt][1] = -1e30f;
                if (kj > r1g)     s[nt][2] = -1e30f;
                if (kj + 1 > r1g) s[nt][3] = -1e30f;
            }
        }

        // online softmax (rows r0g, r1g); quad reductions
        float mt0 = -1e30f, mt1 = -1e30f;
#pragma unroll
        for (int nt = 0; nt < 8; nt++) {
            mt0 = fmaxf(mt0, fmaxf(s[nt][0], s[nt][1]));
            mt1 = fmaxf(mt1, fmaxf(s[nt][2], s[nt][3]));
        }
        mt0 = fmaxf(mt0, __shfl_xor_sync(0xffffffffu, mt0, 1));
        mt0 = fmaxf(mt0, __shfl_xor_sync(0xffffffffu, mt0, 2));
        mt1 = fmaxf(mt1, __shfl_xor_sync(0xffffffffu, mt1, 1));
        mt1 = fmaxf(mt1, __shfl_xor_sync(0xffffffffu, mt1, 2));

        const float mn0 = fmaxf(m0, mt0), mn1 = fmaxf(m1, mt1);
        const float sc0 = __expf(m0 - mn0), sc1 = __expf(m1 - mn1);
        m0 = mn0; m1 = mn1;

        float rs0 = 0.f, rs1 = 0.f;
#pragma unroll
        for (int nt = 0; nt < 8; nt++) {
            s[nt][0] = __expf(s[nt][0] - mn0);
            s[nt][1] = __expf(s[nt][1] - mn0);
            s[nt][2] = __expf(s[nt][2] - mn1);
            s[nt][3] = __expf(s[nt][3] - mn1);
            rs0 += s[nt][0] + s[nt][1];
            rs1 += s[nt][2] + s[nt][3];
        }
        rs0 += __shfl_xor_sync(0xffffffffu, rs0, 1);
        rs0 += __shfl_xor_sync(0xffffffffu, rs0, 2);
        rs1 += __shfl_xor_sync(0xffffffffu, rs1, 1);
        rs1 += __shfl_xor_sync(0xffffffffu, rs1, 2);
        l0 = l0 * sc0 + rs0;
        l1 = l1 * sc1 + rs1;

#pragma unroll
        for (int dt = 0; dt < 8; dt++) {
            o[dt][0] *= sc0; o[dt][1] *= sc0;
            o[dt][2] *= sc1; o[dt][3] *= sc1;
        }

        // O += P @ V : P built register-direct from S (A-frag == D-frag, k16)
#pragma unroll
        for (int kc = 0; kc < 4; kc++) {
            unsigned pa[4];
            pa[0] = h2pack(s[2 * kc][0],     s[2 * kc][1]);
            pa[1] = h2pack(s[2 * kc][2],     s[2 * kc][3]);
            pa[2] = h2pack(s[2 * kc + 1][0], s[2 * kc + 1][1]);
            pa[3] = h2pack(s[2 * kc + 1][2], s[2 * kc + 1][3]);
#pragma unroll
            for (int j = 0; j < 4; j++) {
                unsigned bv[4];
                ldsm4t(bv, Vst + ((kc * 16 + vrow) * AST + j * 16 + vcol) * 2);
                mma16(o[2 * j],     pa, bv[0], bv[1]);
                mma16(o[2 * j + 1], pa, bv[2], bv[3]);
            }
        }
    }

    // epilogue: normalize, write fp16 (feeds final GEMM)
    const float i0 = 1.f / l0, i1 = 1.f / l1;
    const int r0g = q0 + rb + g;
    __half* Ob = AO + (size_t)(b * TT + r0g) * DM + h * DK;
#pragma unroll
    for (int dt = 0; dt < 8; dt++) {
        const int col = dt * 8 + 2 * t;
        *(unsigned*)&Ob[col]          = h2pack(o[dt][0] * i0, o[dt][1] * i0);
        *(unsigned*)&Ob[8 * DM + col] = h2pack(o[dt][2] * i1, o[dt][3] * i1);
    }
}

// ---------------------------------------------------------------------------
// launch: converts -> fused QKV GEMM -> attention -> output GEMM
// input order: q, mask, Wq, bq, Wk, bk, Wv, bv, Wo, bo (mask ignored: causal)
// ---------------------------------------------------------------------------
extern "C" void kernel_launch(void* const* d_in, const int* in_sizes, int n_in,
                              void* d_out, int out_size) {
    (void)in_sizes; (void)n_in; (void)out_size;
    const float* q  = (const float*)d_in[0];
    const float* Wq = (const float*)d_in[2];
    const float* bq = (const float*)d_in[3];
    const float* Wk = (const float*)d_in[4];
    const float* bk = (const float*)d_in[5];
    const float* Wv = (const float*)d_in[6];
    const float* bv = (const float*)d_in[7];
    const float* Wo = (const float*)d_in[8];
    const float* bo = (const float*)d_in[9];
    float* out = (float*)d_out;

    __half *pXh, *pW4, *pQKV, *pAO;
    float* pb3;
    cudaGetSymbolAddress((void**)&pXh, g_Xh);
    cudaGetSymbolAddress((void**)&pW4, g_W4);
    cudaGetSymbolAddress((void**)&pb3, g_b3);
    cudaGetSymbolAddress((void**)&pQKV, g_QKV);
    cudaGetSymbolAddress((void**)&pAO, g_AO);

    cudaFuncSetAttribute(gemm_f16<1>, cudaFuncAttributeMaxDynamicSharedMemorySize,
                         SMEM_GEMM);
    cudaFuncSetAttribute(gemm_f16<0>, cudaFuncAttributeMaxDynamicSharedMemorySize,
                         SMEM_GEMM);
    cudaFuncSetAttribute(attn_f16, cudaFuncAttributeMaxDynamicSharedMemorySize,
                         SMEM_ATTN);

    // fp32 -> fp16 conversions (weights concatenated into one buffer)
    f2h4<<<(NB * TT * DM) / 1024, 256>>>(q, pXh);
    f2h4<<<(DM * DM) / 1024, 256>>>(Wq, pW4 + 0 * DM * DM);
    f2h4<<<(DM * DM) / 1024, 256>>>(Wk, pW4 + 1 * DM * DM);
    f2h4<<<(DM * DM) / 1024, 256>>>(Wv, pW4 + 2 * DM * DM);
    f2h4<<<(DM * DM) / 1024, 256>>>(Wo, pW4 + 3 * DM * DM);
    bias_cat<<<12, 256>>>(bq, bk, bv, pb3);

    // fused Q/K/V projection: C[8192, 3072], Q-columns pre-scaled by 0.125
    gemm_f16<1><<<dim3(3 * DM / GBN, (NB * TT) / GBM), 256, SMEM_GEMM>>>(
        pXh, pW4, pb3, pQKV);

    attn_f16<<<dim3(TT / 128, NB * NH), 256, SMEM_ATTN>>>(pQKV, pAO);

    gemm_f16<0><<<dim3(DM / GBN, (NB * TT) / GBM), 256, SMEM_GEMM>>>(
        pAO, pW4 + 3 * DM * DM, bo, out);
}

// round 8
// speedup vs baseline: 2.4499x; 1.0241x over previous
#include <cuda_runtime.h>
#include <cuda_fp16.h>

#define DM 1024
#define TT 2048
#define NB 4
#define NH 16
#define DK 64

// Scratch (__device__ globals; allocation is forbidden everywhere)
__device__ __half g_Xh[NB * TT * DM];          // fp16 input activations
__device__ __half g_W4[4 * DM * DM];           // fp16 Wq,Wk,Wv,Wo (concat)
__device__ float  g_b3[3 * DM];                // concat bq,bk,bv
__device__ __half g_QKV[NB * TT * 3 * DM];     // fused projection output
__device__ __half g_AO[NB * TT * DM];          // attention output (fp16)

// ---------------------------------------------------------------------------
// helpers
// ---------------------------------------------------------------------------
__device__ __forceinline__ unsigned h2pack(float lo, float hi) {
    unsigned u;
    asm("cvt.rn.f16x2.f32 %0, %1, %2;" : "=r"(u) : "f"(hi), "f"(lo));
    return u;
}
__device__ __forceinline__ float ex2(float x) {
    float y;
    asm("ex2.approx.ftz.f32 %0, %1;" : "=f"(y) : "f"(x));
    return y;
}

__device__ __forceinline__ void mma16(float (&d)[4], const unsigned (&a)[4],
                                      unsigned b0, unsigned b1) {
    asm volatile(
        "mma.sync.aligned.m16n8k16.row.col.f32.f16.f16.f32 "
        "{%0,%1,%2,%3}, {%4,%5,%6,%7}, {%8,%9}, {%0,%1,%2,%3};"
        : "+f"(d[0]), "+f"(d[1]), "+f"(d[2]), "+f"(d[3])
        : "r"(a[0]), "r"(a[1]), "r"(a[2]), "r"(a[3]), "r"(b0), "r"(b1));
}

__device__ __forceinline__ void ldsm4(unsigned (&r)[4], unsigned addr) {
    asm volatile("ldmatrix.sync.aligned.m8n8.x4.shared.b16 {%0,%1,%2,%3}, [%4];"
                 : "=r"(r[0]), "=r"(r[1]), "=r"(r[2]), "=r"(r[3]) : "r"(addr));
}
__device__ __forceinline__ void ldsm4t(unsigned (&r)[4], unsigned addr) {
    asm volatile("ldmatrix.sync.aligned.m8n8.x4.trans.shared.b16 {%0,%1,%2,%3}, [%4];"
                 : "=r"(r[0]), "=r"(r[1]), "=r"(r[2]), "=r"(r[3]) : "r"(addr));
}

__device__ __forceinline__ void cpa16(unsigned sa, const void* g) {
    asm volatile("cp.async.cg.shared.global [%0], [%1], 16;" ::"r"(sa), "l"(g));
}
#define CP_COMMIT asm volatile("cp.async.commit_group;")
#define CP_WAIT(n) asm volatile("cp.async.wait_group %0;" ::"n"(n))

// ---------------------------------------------------------------------------
// elementwise fp32 -> fp16 (4 elts/thread)
// ---------------------------------------------------------------------------
__global__ void f2h4(const float* __restrict__ s, __half* __restrict__ d) {
    int i = (blockIdx.x * 256 + threadIdx.x) * 4;
    float4 v = *(const float4*)&s[i];
    uint2 u;
    u.x = h2pack(v.x, v.y);
    u.y = h2pack(v.z, v.w);
    *(uint2*)&d[i] = u;
}

__global__ void bias_cat(const float* __restrict__ bq, const float* __restrict__ bk,
                         const float* __restrict__ bv, float* __restrict__ d) {
    int i = blockIdx.x * 256 + threadIdx.x;  // 0..3071
    const float* s = (i < DM) ? bq : (i < 2 * DM) ? bk : bv;
    d[i] = s[i & (DM - 1)];
}

// ---------------------------------------------------------------------------
// fp16 GEMM (round-6 proven): C[M,N] = A[M,1024] @ W[N,1024]^T + bias
// Block 128x128, BK=32, 4-stage cp.async, 256 threads, warp tile 32x64.
// QKV=1: fp16 out, row stride 3072, Q-cols (cb<DM) scaled by 0.125*log2e.
// ---------------------------------------------------------------------------
#define GBM 128
#define GBN 128
#define GBK 32
#define GST 40
#define GSTG ((GBM + GBN) * GST)      // halves per stage (10240)
#define SMEM_GEMM (4 * GSTG * 2)      // 81920 B
#define QSCALE 0.180336884f           // 0.125 * log2(e): feeds exp2 softmax

template <int QKV>
__global__ __launch_bounds__(256, 2) void gemm_f16(
    const __half* __restrict__ A, const __half* __restrict__ W,
    const float* __restrict__ bias, void* __restrict__ Cv) {
    extern __shared__ __half sh[];
    const unsigned sbase = (unsigned)__cvta_generic_to_shared(sh);

    const int tid  = threadIdx.x;
    const int lane = tid & 31;
    const int wid  = tid >> 5;
    const int g    = lane >> 2;
    const int t    = lane & 3;
    const int wm   = (wid >> 1) * 32;
    const int wn   = (wid & 1) * 64;
    const int bm0  = blockIdx.y * GBM;
    const int bn0  = blockIdx.x * GBN;
    const int OST  = QKV ? 3 * DM : DM;

    float acc[2][8][4];
#pragma unroll
    for (int i = 0; i < 2; i++)
#pragma unroll
        for (int j = 0; j < 8; j++)
#pragma unroll
            for (int k = 0; k < 4; k++) acc[i][j][k] = 0.f;

    auto load_stage = [&](int st, int kt) {
        unsigned as = sbase + st * GSTG * 2;
        unsigned bs = as + GBM * GST * 2;
        const int kb = kt * GBK;
#pragma unroll
        for (int i = 0; i < 2; i++) {
            int c = tid + i * 256;
            int r = c >> 2, kc = (c & 3) * 8;
            cpa16(as + (r * GST + kc) * 2, &A[(size_t)(bm0 + r) * DM + kb + kc]);
        }
#pragma unroll
        for (int i = 0; i < 2; i++) {
            int c = tid + i * 256;
            int r = c >> 2, kc = (c & 3) * 8;
            cpa16(bs + (r * GST + kc) * 2, &W[(size_t)(bn0 + r) * DM + kb + kc]);
        }
        CP_COMMIT;
    };

    const int arow  = (lane & 7) + ((lane >> 3) & 1) * 8;
    const int akoff = (lane >> 4) * 8;
    const int brow  = ((lane >> 4) & 1) * 8 + (lane & 7);
    const int bkoff = ((lane >> 3) & 1) * 8;

    load_stage(0, 0);
    load_stage(1, 1);
    load_stage(2, 2);

    const int NT = DM / GBK;  // 32
    for (int kt = 0; kt < NT; kt++) {
        if (kt + 2 < NT)      { CP_WAIT(2); }
        else if (kt + 1 < NT) { CP_WAIT(1); }
        else                  { CP_WAIT(0); }
        __syncthreads();
        if (kt + 3 < NT) load_stage((kt + 3) & 3, kt + 3);

        unsigned as = sbase + (kt & 3) * GSTG * 2;
        unsigned bs = as + GBM * GST * 2;
#pragma unroll
        for (int ks = 0; ks < 2; ks++) {
            const int k0 = ks * 16;
            unsigned a[2][4];
#pragma unroll
            for (int mt = 0; mt < 2; mt++)
                ldsm4(a[mt], as + ((wm + mt * 16 + arow) * GST + k0 + akoff) * 2);
#pragma unroll
            for (int j = 0; j < 4; j++) {
                unsigned bf[4];
                ldsm4(bf, bs + ((wn + j * 16 + brow) * GST + k0 + bkoff) * 2);
#pragma unroll
                for (int mt = 0; mt < 2; mt++) {
                    mma16(acc[mt][2 * j],     a[mt], bf[0], bf[1]);
                    mma16(acc[mt][2 * j + 1], a[mt], bf[2], bf[3]);
                }
            }
        }
    }

#pragma unroll
    for (int mt = 0; mt < 2; mt++) {
#pragma unroll
        for (int nt = 0; nt < 8; nt++) {
            const int r0 = bm0 + wm + mt * 16 + g;
            const int cb = bn0 + wn + nt * 8 + 2 * t;
            const float b0 = bias[cb], b1 = bias[cb + 1];
            if (QKV) {
                const float sc = (cb < DM) ? QSCALE : 1.f;
                __half* C = (__half*)Cv;
                *(unsigned*)&C[(size_t)r0 * OST + cb] =
                    h2pack((acc[mt][nt][0] + b0) * sc, (acc[mt][nt][1] + b1) * sc);
                *(unsigned*)&C[(size_t)(r0 + 8) * OST + cb] =
                    h2pack((acc[mt][nt][2] + b0) * sc, (acc[mt][nt][3] + b1) * sc);
            } else {
                float* C = (float*)Cv;
                float2 v;
                v.x = acc[mt][nt][0] + b0;
                v.y = acc[mt][nt][1] + b1;
                *(float2*)&C[(size_t)r0 * OST + cb] = v;
                v.x = acc[mt][nt][2] + b0;
                v.y = acc[mt][nt][3] + b1;
                *(float2*)&C[(size_t)(r0 + 8) * OST + cb] = v;
            }
        }
    }
}

// ---------------------------------------------------------------------------
// Causal flash attention, fp16 m16n8k16.
// CTA = 256 q-rows of one (b,h), 8 warps, 32 q-rows/warp (2 m-groups).
// 64-key K/V tiles, 3-stage cp.async ring. V-frags shared across m-groups.
// Per-warp FULL SKIP of key tiles entirely above the warp's row band.
// Softmax in log2 domain (Q pre-scaled by 0.125*log2e), ex2.approx.
// Smem row stride 72 halves: conflict-free ldmatrix.
// ---------------------------------------------------------------------------
#define BQ 256
#define AST 72
#define AK_OFF (BQ * AST)
#define AV_OFF (AK_OFF + 3 * 64 * AST)
#define SMEM_ATTN ((AV_OFF + 3 * 64 * AST) * 2)   // 92160 B

__global__ __launch_bounds__(256, 1) void attn_f16(
    const __half* __restrict__ QKV, __half* __restrict__ AO) {
    extern __shared__ __half sh[];
    const unsigned sbase = (unsigned)__cvta_generic_to_shared(sh);

    const int tid  = threadIdx.x;
    const int lane = tid & 31;
    const int wid  = tid >> 5;
    const int g    = lane >> 2;
    const int t    = lane & 3;
    const int rb   = wid * 32;                    // warp's 32-row band
    const int qtx  = gridDim.x - 1 - blockIdx.x;  // heavy causal tiles first
    const int bh   = blockIdx.y;
    const int b    = bh >> 4;
    const int h    = bh & 15;
    const int q0   = qtx * BQ;

    const __half* Qb = QKV + (size_t)(b * TT) * 3 * DM + h * DK;
    const __half* Kb = Qb + DM;
    const __half* Vb = Qb + 2 * DM;

    auto ldKV = [&](int kt, int st) {
#pragma unroll
        for (int i = 0; i < 2; i++) {
            int c = tid + i * 256;
            int r = c >> 3, kc = (c & 7) * 8;
            size_t gro = (size_t)(kt * 64 + r) * 3 * DM + kc;
            cpa16(sbase + (AK_OFF + st * 64 * AST + r * AST + kc) * 2, Kb + gro);
            cpa16(sbase + (AV_OFF + st * 64 * AST + r * AST + kc) * 2, Vb + gro);
        }
    };

    const int nkt = 4 * qtx + 4;  // keys up to q0+255
    {   // Q tile (256 rows) + KV tile 0 -> group 0; KV tile 1 -> group 1
#pragma unroll
        for (int i = 0; i < 8; i++) {
            int c = tid + i * 256;
            int r = c >> 3, kc = (c & 7) * 8;
            cpa16(sbase + (r * AST + kc) * 2, Qb + (size_t)(q0 + r) * 3 * DM + kc);
        }
        ldKV(0, 0);
        CP_COMMIT;
        ldKV(1, 1);
        CP_COMMIT;
    }

    float o[2][8][4];
#pragma unroll
    for (int mg = 0; mg < 2; mg++)
#pragma unroll
        for (int i = 0; i < 8; i++)
#pragma unroll
            for (int j = 0; j < 4; j++) o[mg][i][j] = 0.f;
    float mr[2][2], lr[2][2];
#pragma unroll
    for (int mg = 0; mg < 2; mg++) {
        mr[mg][0] = -1e30f; mr[mg][1] = -1e30f;
        lr[mg][0] = 0.f;    lr[mg][1] = 0.f;
    }

    const int arow  = (lane & 7) + ((lane >> 3) & 1) * 8;
    const int akoff = (lane >> 4) * 8;
    const int brow  = ((lane >> 4) & 1) * 8 + (lane & 7);
    const int bkoff = ((lane >> 3) & 1) * 8;
    const int vrow  = (lane & 7) + ((lane >> 3) & 1) * 8;
    const int vcol  = ((lane >> 4) & 1) * 8;

    for (int kt = 0; kt < nkt; kt++) {
        if (kt + 1 < nkt) { CP_WAIT(1); } else { CP_WAIT(0); }
        __syncthreads();
        if (kt + 2 < nkt) { ldKV(kt + 2, (kt + 2) % 3); CP_COMMIT; }

        // per-warp full skip: all 64 keys above every row of this band
        if (kt * 64 > q0 + rb + 31) continue;

        const unsigned Kst = sbase + (AK_OFF + (kt % 3) * 64 * AST) * 2;
        const unsigned Vst = sbase + (AV_OFF + (kt % 3) * 64 * AST) * 2;

        // S = Q @ K^T : 32 q-rows x 64 keys per warp
        float s[2][8][4];
#pragma unroll
        for (int mg = 0; mg < 2; mg++)
#pragma unroll
            for (int i = 0; i < 8; i++)
#pragma unroll
                for (int j = 0; j < 4; j++) s[mg][i][j] = 0.f;

#pragma unroll
        for (int ks = 0; ks < 4; ks++) {
            const int k0 = ks * 16;
            unsigned a[2][4];
            ldsm4(a[0], sbase + ((rb + arow) * AST + k0 + akoff) * 2);
            ldsm4(a[1], sbase + ((rb + 16 + arow) * AST + k0 + akoff) * 2);
#pragma unroll
            for (int j = 0; j < 4; j++) {
                unsigned bf[4];
                ldsm4(bf, Kst + ((j * 16 + brow) * AST + k0 + bkoff) * 2);
#pragma unroll
                for (int mg = 0; mg < 2; mg++) {
                    mma16(s[mg][2 * j],     a[mg], bf[0], bf[1]);
                    mma16(s[mg][2 * j + 1], a[mg], bf[2], bf[3]);
                }
            }
        }

        if (kt * 64 + 63 > q0 + rb) {  // diagonal tile: mask
#pragma unroll
            for (int mg = 0; mg < 2; mg++) {
                const int r0g = q0 + rb + mg * 16 + g;
                const int r1g = r0g + 8;
#pragma unroll
                for (int nt = 0; nt < 8; nt++) {
                    int kj = kt * 64 + nt * 8 + 2 * t;
                    if (kj > r0g)     s[mg][nt][0] = -1e30f;
                    if (kj + 1 > r0g) s[mg][nt][1] = -1e30f;
                    if (kj > r1g)     s[mg][nt][2] = -1e30f;
                    if (kj + 1 > r1g) s[mg][nt][3] = -1e30f;
                }
            }
        }

        // online softmax per m-group (log2 domain)
#pragma unroll
        for (int mg = 0; mg < 2; mg++) {
            float mt0 = -1e30f, mt1 = -1e30f;
#pragma unroll
            for (int nt = 0; nt < 8; nt++) {
                mt0 = fmaxf(mt0, fmaxf(s[mg][nt][0], s[mg][nt][1]));
                mt1 = fmaxf(mt1, fmaxf(s[mg][nt][2], s[mg][nt][3]));
            }
            mt0 = fmaxf(mt0, __shfl_xor_sync(0xffffffffu, mt0, 1));
            mt0 = fmaxf(mt0, __shfl_xor_sync(0xffffffffu, mt0, 2));
            mt1 = fmaxf(mt1, __shfl_xor_sync(0xffffffffu, mt1, 1));
            mt1 = fmaxf(mt1, __shfl_xor_sync(0xffffffffu, mt1, 2));

            const float mn0 = fmaxf(mr[mg][0], mt0), mn1 = fmaxf(mr[mg][1], mt1);
            const float sc0 = ex2(mr[mg][0] - mn0), sc1 = ex2(mr[mg][1] - mn1);
            mr[mg][0] = mn0; mr[mg][1] = mn1;

            float rs0 = 0.f, rs1 = 0.f;
#pragma unroll
            for (int nt = 0; nt < 8; nt++) {
                s[mg][nt][0] = ex2(s[mg][nt][0] - mn0);
                s[mg][nt][1] = ex2(s[mg][nt][1] - mn0);
                s[mg][nt][2] = ex2(s[mg][nt][2] - mn1);
                s[mg][nt][3] = ex2(s[mg][nt][3] - mn1);
                rs0 += s[mg][nt][0] + s[mg][nt][1];
                rs1 += s[mg][nt][2] + s[mg][nt][3];
            }
            rs0 += __shfl_xor_sync(0xffffffffu, rs0, 1);
            rs0 += __shfl_xor_sync(0xffffffffu, rs0, 2);
            rs1 += __shfl_xor_sync(0xffffffffu, rs1, 1);
            rs1 += __shfl_xor_sync(0xffffffffu, rs1, 2);
            lr[mg][0] = lr[mg][0] * sc0 + rs0;
            lr[mg][1] = lr[mg][1] * sc1 + rs1;

#pragma unroll
            for (int dt = 0; dt < 8; dt++) {
                o[mg][dt][0] *= sc0; o[mg][dt][1] *= sc0;
                o[mg][dt][2] *= sc1; o[mg][dt][3] *= sc1;
            }
        }

        // O += P @ V : P register-direct; V-frags shared across m-groups
#pragma unroll
        for (int kc = 0; kc < 4; kc++) {
            unsigned pa[2][4];
#pragma unroll
            for (int mg = 0; mg < 2; mg++) {
                pa[mg][0] = h2pack(s[mg][2 * kc][0],     s[mg][2 * kc][1]);
                pa[mg][1] = h2pack(s[mg][2 * kc][2],     s[mg][2 * kc][3]);
                pa[mg][2] = h2pack(s[mg][2 * kc + 1][0], s[mg][2 * kc + 1][1]);
                pa[mg][3] = h2pack(s[mg][2 * kc + 1][2], s[mg][2 * kc + 1][3]);
            }
#pragma unroll
            for (int j = 0; j < 4; j++) {
                unsigned bv[4];
                ldsm4t(bv, Vst + ((kc * 16 + vrow) * AST + j * 16 + vcol) * 2);
#pragma unroll
                for (int mg = 0; mg < 2; mg++) {
                    mma16(o[mg][2 * j],     pa[mg], bv[0], bv[1]);
                    mma16(o[mg][2 * j + 1], pa[mg], bv[2], bv[3]);
                }
            }
        }
    }

    // epilogue: normalize, write fp16 (feeds final GEMM)
#pragma unroll
    for (int mg = 0; mg < 2; mg++) {
        const float i0 = 1.f / lr[mg][0], i1 = 1.f / lr[mg][1];
        const int r0g = q0 + rb + mg * 16 + g;
        __half* Ob = AO + (size_t)(b * TT + r0g) * DM + h * DK;
#pragma unroll
        for (int dt = 0; dt < 8; dt++) {
            const int col = dt * 8 + 2 * t;
            *(unsigned*)&Ob[col] =
                h2pack(o[mg][dt][0] * i0, o[mg][dt][1] * i0);
            *(unsigned*)&Ob[8 * DM + col] =
                h2pack(o[mg][dt][2] * i1, o[mg][dt][3] * i1);
        }
    }
}

// ---------------------------------------------------------------------------
// launch: converts -> fused QKV GEMM -> attention -> output GEMM
// input order: q, mask, Wq, bq, Wk, bk, Wv, bv, Wo, bo (mask ignored: causal)
// ---------------------------------------------------------------------------
extern "C" void kernel_launch(void* const* d_in, const int* in_sizes, int n_in,
                              void* d_out, int out_size) {
    (void)in_sizes; (void)n_in; (void)out_size;
    const float* q  = (const float*)d_in[0];
    const float* Wq = (const float*)d_in[2];
    const float* bq = (const float*)d_in[3];
    const float* Wk = (const float*)d_in[4];
    const float* bk = (const float*)d_in[5];
    const float* Wv = (const float*)d_in[6];
    const float* bv = (const float*)d_in[7];
    const float* Wo = (const float*)d_in[8];
    const float* bo = (const float*)d_in[9];
    float* out = (float*)d_out;

    __half *pXh, *pW4, *pQKV, *pAO;
    float* pb3;
    cudaGetSymbolAddress((void**)&pXh, g_Xh);
    cudaGetSymbolAddress((void**)&pW4, g_W4);
    cudaGetSymbolAddress((void**)&pb3, g_b3);
    cudaGetSymbolAddress((void**)&pQKV, g_QKV);
    cudaGetSymbolAddress((void**)&pAO, g_AO);

    cudaFuncSetAttribute(gemm_f16<1>, cudaFuncAttributeMaxDynamicSharedMemorySize,
                         SMEM_GEMM);
    cudaFuncSetAttribute(gemm_f16<0>, cudaFuncAttributeMaxDynamicSharedMemorySize,
                         SMEM_GEMM);
    cudaFuncSetAttribute(attn_f16, cudaFuncAttributeMaxDynamicSharedMemorySize,
                         SMEM_ATTN);

    // fp32 -> fp16 conversions (weights concatenated into one buffer)
    f2h4<<<(NB * TT * DM) / 1024, 256>>>(q, pXh);
    f2h4<<<(DM * DM) / 1024, 256>>>(Wq, pW4 + 0 * DM * DM);
    f2h4<<<(DM * DM) / 1024, 256>>>(Wk, pW4 + 1 * DM * DM);
    f2h4<<<(DM * DM) / 1024, 256>>>(Wv, pW4 + 2 * DM * DM);
    f2h4<<<(DM * DM) / 1024, 256>>>(Wo, pW4 + 3 * DM * DM);
    bias_cat<<<12, 256>>>(bq, bk, bv, pb3);

    // fused QKV projection: Q-cols pre-scaled by 0.125*log2e for exp2 softmax
    gemm_f16<1><<<dim3(3 * DM / GBN, (NB * TT) / GBM), 256, SMEM_GEMM>>>(
        pXh, pW4, pb3, pQKV);

    attn_f16<<<dim3(TT / BQ, NB * NH), 256, SMEM_ATTN>>>(pQKV, pAO);

    gemm_f16<0><<<dim3(DM / GBN, (NB * TT) / GBM), 256, SMEM_GEMM>>>(
        pAO, pW4 + 3 * DM * DM, bo, out);
}

// round 9
// speedup vs baseline: 2.6199x; 1.0694x over previous
#include <cuda_runtime.h>
#include <cuda_fp16.h>

#define DM 1024
#define TT 2048
#define NB 4
#define NH 16
#define DK 64

// Scratch (__device__ globals; allocation is forbidden everywhere)
__device__ __half g_Xh[NB * TT * DM];          // fp16 input activations
__device__ __half g_W4[4 * DM * DM];           // fp16 Wq,Wk,Wv,Wo (concat)
__device__ float  g_b3[3 * DM];                // concat bq,bk,bv
__device__ __half g_QKV[NB * TT * 3 * DM];     // fused projection output
__device__ __half g_AO[NB * TT * DM];          // attention output (fp16)

// ---------------------------------------------------------------------------
// helpers
// ---------------------------------------------------------------------------
__device__ __forceinline__ unsigned h2pack(float lo, float hi) {
    unsigned u;
    asm("cvt.rn.f16x2.f32 %0, %1, %2;" : "=r"(u) : "f"(hi), "f"(lo));
    return u;
}
__device__ __forceinline__ float ex2(float x) {
    float y;
    asm("ex2.approx.ftz.f32 %0, %1;" : "=f"(y) : "f"(x));
    return y;
}

__device__ __forceinline__ void mma16(float (&d)[4], const unsigned (&a)[4],
                                      unsigned b0, unsigned b1) {
    asm volatile(
        "mma.sync.aligned.m16n8k16.row.col.f32.f16.f16.f32 "
        "{%0,%1,%2,%3}, {%4,%5,%6,%7}, {%8,%9}, {%0,%1,%2,%3};"
        : "+f"(d[0]), "+f"(d[1]), "+f"(d[2]), "+f"(d[3])
        : "r"(a[0]), "r"(a[1]), "r"(a[2]), "r"(a[3]), "r"(b0), "r"(b1));
}

__device__ __forceinline__ void ldsm4(unsigned (&r)[4], unsigned addr) {
    asm volatile("ldmatrix.sync.aligned.m8n8.x4.shared.b16 {%0,%1,%2,%3}, [%4];"
                 : "=r"(r[0]), "=r"(r[1]), "=r"(r[2]), "=r"(r[3]) : "r"(addr));
}
__device__ __forceinline__ void ldsm4t(unsigned (&r)[4], unsigned addr) {
    asm volatile("ldmatrix.sync.aligned.m8n8.x4.trans.shared.b16 {%0,%1,%2,%3}, [%4];"
                 : "=r"(r[0]), "=r"(r[1]), "=r"(r[2]), "=r"(r[3]) : "r"(addr));
}

__device__ __forceinline__ void cpa16(unsigned sa, const void* g) {
    asm volatile("cp.async.cg.shared.global [%0], [%1], 16;" ::"r"(sa), "l"(g));
}
#define CP_COMMIT asm volatile("cp.async.commit_group;")
#define CP_WAIT(n) asm volatile("cp.async.wait_group %0;" ::"n"(n))

// ---------------------------------------------------------------------------
// elementwise fp32 -> fp16 (4 elts/thread)
// ---------------------------------------------------------------------------
__global__ void f2h4(const float* __restrict__ s, __half* __restrict__ d) {
    int i = (blockIdx.x * 256 + threadIdx.x) * 4;
    float4 v = *(const float4*)&s[i];
    uint2 u;
    u.x = h2pack(v.x, v.y);
    u.y = h2pack(v.z, v.w);
    *(uint2*)&d[i] = u;
}

__global__ void bias_cat(const float* __restrict__ bq, const float* __restrict__ bk,
                         const float* __restrict__ bv, float* __restrict__ d) {
    int i = blockIdx.x * 256 + threadIdx.x;  // 0..3071
    const float* s = (i < DM) ? bq : (i < 2 * DM) ? bk : bv;
    d[i] = s[i & (DM - 1)];
}

// ---------------------------------------------------------------------------
// fp16 GEMM: C[M,N] = A[M,1024] @ W[N,1024]^T + bias
// Block 128x128, BK=32, 3-stage cp.async, 128 threads, warp tile 64x64
// (CUTLASS sm80 shape: 128 fp32 acc/thread, HMMA:LDSM = 4.0, 2 CTAs/SM).
// QKV=1: fp16 out, row stride 3072, Q-cols (cb<DM) scaled by 0.125*log2e.
// ---------------------------------------------------------------------------
#define GBM 128
#define GBN 128
#define GBK 32
#define GST 40
#define GSTG ((GBM + GBN) * GST)      // halves per stage (10240)
#define SMEM_GEMM (3 * GSTG * 2)      // 61440 B
#define QSCALE 0.180336884f           // 0.125 * log2(e): feeds exp2 softmax

template <int QKV>
__global__ __launch_bounds__(128, 2) void gemm_f16(
    const __half* __restrict__ A, const __half* __restrict__ W,
    const float* __restrict__ bias, void* __restrict__ Cv) {
    extern __shared__ __half sh[];
    const unsigned sbase = (unsigned)__cvta_generic_to_shared(sh);

    const int tid  = threadIdx.x;
    const int lane = tid & 31;
    const int wid  = tid >> 5;
    const int g    = lane >> 2;
    const int t    = lane & 3;
    const int wm   = (wid >> 1) * 64;
    const int wn   = (wid & 1) * 64;
    const int bm0  = blockIdx.y * GBM;
    const int bn0  = blockIdx.x * GBN;
    const int OST  = QKV ? 3 * DM : DM;

    float acc[4][8][4];
#pragma unroll
    for (int i = 0; i < 4; i++)
#pragma unroll
        for (int j = 0; j < 8; j++)
#pragma unroll
            for (int k = 0; k < 4; k++) acc[i][j][k] = 0.f;

    auto load_stage = [&](int st, int kt) {
        unsigned as = sbase + st * GSTG * 2;
        unsigned bs = as + GBM * GST * 2;
        const int kb = kt * GBK;
#pragma unroll
        for (int i = 0; i < 4; i++) {       // A: 512 16B chunks / 128 thr
            int c = tid + i * 128;
            int r = c >> 2, kc = (c & 3) * 8;
            cpa16(as + (r * GST + kc) * 2, &A[(size_t)(bm0 + r) * DM + kb + kc]);
        }
#pragma unroll
        for (int i = 0; i < 4; i++) {       // B: 512 chunks
            int c = tid + i * 128;
            int r = c >> 2, kc = (c & 3) * 8;
            cpa16(bs + (r * GST + kc) * 2, &W[(size_t)(bn0 + r) * DM + kb + kc]);
        }
        CP_COMMIT;
    };

    const int arow  = (lane & 7) + ((lane >> 3) & 1) * 8;
    const int akoff = (lane >> 4) * 8;
    const int brow  = ((lane >> 4) & 1) * 8 + (lane & 7);
    const int bkoff = ((lane >> 3) & 1) * 8;

    load_stage(0, 0);
    load_stage(1, 1);
    load_stage(2, 2);

    const int NT = DM / GBK;  // 32
    for (int kt = 0; kt < NT; kt++) {
        if (kt + 2 < NT)      { CP_WAIT(2); }
        else if (kt + 1 < NT) { CP_WAIT(1); }
        else                  { CP_WAIT(0); }
        __syncthreads();
        const int st = kt % 3;
        unsigned as = sbase + st * GSTG * 2;
        unsigned bs = as + GBM * GST * 2;
#pragma unroll
        for (int ks = 0; ks < 2; ks++) {
            const int k0 = ks * 16;
            unsigned a[4][4];
#pragma unroll
            for (int mt = 0; mt < 4; mt++)
                ldsm4(a[mt], as + ((wm + mt * 16 + arow) * GST + k0 + akoff) * 2);
#pragma unroll
            for (int j = 0; j < 4; j++) {
                unsigned bf[4];
                ldsm4(bf, bs + ((wn + j * 16 + brow) * GST + k0 + bkoff) * 2);
#pragma unroll
                for (int mt = 0; mt < 4; mt++) {
                    mma16(acc[mt][2 * j],     a[mt], bf[0], bf[1]);
                    mma16(acc[mt][2 * j + 1], a[mt], bf[2], bf[3]);
                }
            }
        }
        __syncthreads();
        if (kt + 3 < NT) load_stage(st, kt + 3);
    }

#pragma unroll
    for (int mt = 0; mt < 4; mt++) {
#pragma unroll
        for (int nt = 0; nt < 8; nt++) {
            const int r0 = bm0 + wm + mt * 16 + g;
            const int cb = bn0 + wn + nt * 8 + 2 * t;
            const float b0 = bias[cb], b1 = bias[cb + 1];
            if (QKV) {
                const float sc = (cb < DM) ? QSCALE : 1.f;
                __half* C = (__half*)Cv;
                *(unsigned*)&C[(size_t)r0 * OST + cb] =
                    h2pack((acc[mt][nt][0] + b0) * sc, (acc[mt][nt][1] + b1) * sc);
                *(unsigned*)&C[(size_t)(r0 + 8) * OST + cb] =
                    h2pack((acc[mt][nt][2] + b0) * sc, (acc[mt][nt][3] + b1) * sc);
            } else {
                float* C = (float*)Cv;
                float2 v;
                v.x = acc[mt][nt][0] + b0;
                v.y = acc[mt][nt][1] + b1;
                *(float2*)&C[(size_t)r0 * OST + cb] = v;
                v.x = acc[mt][nt][2] + b0;
                v.y = acc[mt][nt][3] + b1;
                *(float2*)&C[(size_t)(r0 + 8) * OST + cb] = v;
            }
        }
    }
}

// ---------------------------------------------------------------------------
// Causal flash attention, fp16 m16n8k16 (unchanged from round 8 — proven).
// CTA = 256 q-rows of one (b,h), 8 warps, 32 q-rows/warp (2 m-groups).
// ---------------------------------------------------------------------------
#define BQ 256
#define AST 72
#define AK_OFF (BQ * AST)
#define AV_OFF (AK_OFF + 3 * 64 * AST)
#define SMEM_ATTN ((AV_OFF + 3 * 64 * AST) * 2)   // 92160 B

__global__ __launch_bounds__(256, 1) void attn_f16(
    const __half* __restrict__ QKV, __half* __restrict__ AO) {
    extern __shared__ __half sh[];
    const unsigned sbase = (unsigned)__cvta_generic_to_shared(sh);

    const int tid  = threadIdx.x;
    const int lane = tid & 31;
    const int wid  = tid >> 5;
    const int g    = lane >> 2;
    const int t    = lane & 3;
    const int rb   = wid * 32;
    const int qtx  = gridDim.x - 1 - blockIdx.x;
    const int bh   = blockIdx.y;
    const int b    = bh >> 4;
    const int h    = bh & 15;
    const int q0   = qtx * BQ;

    const __half* Qb = QKV + (size_t)(b * TT) * 3 * DM + h * DK;
    const __half* Kb = Qb + DM;
    const __half* Vb = Qb + 2 * DM;

    auto ldKV = [&](int kt, int st) {
#pragma unroll
        for (int i = 0; i < 2; i++) {
            int c = tid + i * 256;
            int r = c >> 3, kc = (c & 7) * 8;
            size_t gro = (size_t)(kt * 64 + r) * 3 * DM + kc;
            cpa16(sbase + (AK_OFF + st * 64 * AST + r * AST + kc) * 2, Kb + gro);
            cpa16(sbase + (AV_OFF + st * 64 * AST + r * AST + kc) * 2, Vb + gro);
        }
    };

    const int nkt = 4 * qtx + 4;
    {
#pragma unroll
        for (int i = 0; i < 8; i++) {
            int c = tid + i * 256;
            int r = c >> 3, kc = (c & 7) * 8;
            cpa16(sbase + (r * AST + kc) * 2, Qb + (size_t)(q0 + r) * 3 * DM + kc);
        }
        ldKV(0, 0);
        CP_COMMIT;
        ldKV(1, 1);
        CP_COMMIT;
    }

    float o[2][8][4];
#pragma unroll
    for (int mg = 0; mg < 2; mg++)
#pragma unroll
        for (int i = 0; i < 8; i++)
#pragma unroll
            for (int j = 0; j < 4; j++) o[mg][i][j] = 0.f;
    float mr[2][2], lr[2][2];
#pragma unroll
    for (int mg = 0; mg < 2; mg++) {
        mr[mg][0] = -1e30f; mr[mg][1] = -1e30f;
        lr[mg][0] = 0.f;    lr[mg][1] = 0.f;
    }

    const int arow  = (lane & 7) + ((lane >> 3) & 1) * 8;
    const int akoff = (lane >> 4) * 8;
    const int brow  = ((lane >> 4) & 1) * 8 + (lane & 7);
    const int bkoff = ((lane >> 3) & 1) * 8;
    const int vrow  = (lane & 7) + ((lane >> 3) & 1) * 8;
    const int vcol  = ((lane >> 4) & 1) * 8;

    for (int kt = 0; kt < nkt; kt++) {
        if (kt + 1 < nkt) { CP_WAIT(1); } else { CP_WAIT(0); }
        __syncthreads();
        if (kt + 2 < nkt) { ldKV(kt + 2, (kt + 2) % 3); CP_COMMIT; }

        if (kt * 64 > q0 + rb + 31) continue;  // fully-masked for this warp

        const unsigned Kst = sbase + (AK_OFF + (kt % 3) * 64 * AST) * 2;
        const unsigned Vst = sbase + (AV_OFF + (kt % 3) * 64 * AST) * 2;

        float s[2][8][4];
#pragma unroll
        for (int mg = 0; mg < 2; mg++)
#pragma unroll
            for (int i = 0; i < 8; i++)
#pragma unroll
                for (int j = 0; j < 4; j++) s[mg][i][j] = 0.f;

#pragma unroll
        for (int ks = 0; ks < 4; ks++) {
            const int k0 = ks * 16;
            unsigned a[2][4];
            ldsm4(a[0], sbase + ((rb + arow) * AST + k0 + akoff) * 2);
            ldsm4(a[1], sbase + ((rb + 16 + arow) * AST + k0 + akoff) * 2);
#pragma unroll
            for (int j = 0; j < 4; j++) {
                unsigned bf[4];
                ldsm4(bf, Kst + ((j * 16 + brow) * AST + k0 + bkoff) * 2);
#pragma unroll
                for (int mg = 0; mg < 2; mg++) {
                    mma16(s[mg][2 * j],     a[mg], bf[0], bf[1]);
                    mma16(s[mg][2 * j + 1], a[mg], bf[2], bf[3]);
                }
            }
        }

        if (kt * 64 + 63 > q0 + rb) {
#pragma unroll
            for (int mg = 0; mg < 2; mg++) {
                const int r0g = q0 + rb + mg * 16 + g;
                const int r1g = r0g + 8;
#pragma unroll
                for (int nt = 0; nt < 8; nt++) {
                    int kj = kt * 64 + nt * 8 + 2 * t;
                    if (kj > r0g)     s[mg][nt][0] = -1e30f;
                    if (kj + 1 > r0g) s[mg][nt][1] = -1e30f;
                    if (kj > r1g)     s[mg][nt][2] = -1e30f;
                    if (kj + 1 > r1g) s[mg][nt][3] = -1e30f;
                }
            }
        }

#pragma unroll
        for (int mg = 0; mg < 2; mg++) {
            float mt0 = -1e30f, mt1 = -1e30f;
#pragma unroll
            for (int nt = 0; nt < 8; nt++) {
                mt0 = fmaxf(mt0, fmaxf(s[mg][nt][0], s[mg][nt][1]));
                mt1 = fmaxf(mt1, fmaxf(s[mg][nt][2], s[mg][nt][3]));
            }
            mt0 = fmaxf(mt0, __shfl_xor_sync(0xffffffffu, mt0, 1));
            mt0 = fmaxf(mt0, __shfl_xor_sync(0xffffffffu, mt0, 2));
            mt1 = fmaxf(mt1, __shfl_xor_sync(0xffffffffu, mt1, 1));
            mt1 = fmaxf(mt1, __shfl_xor_sync(0xffffffffu, mt1, 2));

            const float mn0 = fmaxf(mr[mg][0], mt0), mn1 = fmaxf(mr[mg][1], mt1);
            const float sc0 = ex2(mr[mg][0] - mn0), sc1 = ex2(mr[mg][1] - mn1);
            mr[mg][0] = mn0; mr[mg][1] = mn1;

            float rs0 = 0.f, rs1 = 0.f;
#pragma unroll
            for (int nt = 0; nt < 8; nt++) {
                s[mg][nt][0] = ex2(s[mg][nt][0] - mn0);
                s[mg][nt][1] = ex2(s[mg][nt][1] - mn0);
                s[mg][nt][2] = ex2(s[mg][nt][2] - mn1);
                s[mg][nt][3] = ex2(s[mg][nt][3] - mn1);
                rs0 += s[mg][nt][0] + s[mg][nt][1];
                rs1 += s[mg][nt][2] + s[mg][nt][3];
            }
            rs0 += __shfl_xor_sync(0xffffffffu, rs0, 1);
            rs0 += __shfl_xor_sync(0xffffffffu, rs0, 2);
            rs1 += __shfl_xor_sync(0xffffffffu, rs1, 1);
            rs1 += __shfl_xor_sync(0xffffffffu, rs1, 2);
            lr[mg][0] = lr[mg][0] * sc0 + rs0;
            lr[mg][1] = lr[mg][1] * sc1 + rs1;

#pragma unroll
            for (int dt = 0; dt < 8; dt++) {
                o[mg][dt][0] *= sc0; o[mg][dt][1] *= sc0;
                o[mg][dt][2] *= sc1; o[mg][dt][3] *= sc1;
            }
        }

#pragma unroll
        for (int kc = 0; kc < 4; kc++) {
            unsigned pa[2][4];
#pragma unroll
            for (int mg = 0; mg < 2; mg++) {
                pa[mg][0] = h2pack(s[mg][2 * kc][0],     s[mg][2 * kc][1]);
                pa[mg][1] = h2pack(s[mg][2 * kc][2],     s[mg][2 * kc][3]);
                pa[mg][2] = h2pack(s[mg][2 * kc + 1][0], s[mg][2 * kc + 1][1]);
                pa[mg][3] = h2pack(s[mg][2 * kc + 1][2], s[mg][2 * kc + 1][3]);
            }
#pragma unroll
            for (int j = 0; j < 4; j++) {
                unsigned bv[4];
                ldsm4t(bv, Vst + ((kc * 16 + vrow) * AST + j * 16 + vcol) * 2);
#pragma unroll
                for (int mg = 0; mg < 2; mg++) {
                    mma16(o[mg][2 * j],     pa[mg], bv[0], bv[1]);
                    mma16(o[mg][2 * j + 1], pa[mg], bv[2], bv[3]);
                }
            }
        }
    }

#pragma unroll
    for (int mg = 0; mg < 2; mg++) {
        const float i0 = 1.f / lr[mg][0], i1 = 1.f / lr[mg][1];
        const int r0g = q0 + rb + mg * 16 + g;
        __half* Ob = AO + (size_t)(b * TT + r0g) * DM + h * DK;
#pragma unroll
        for (int dt = 0; dt < 8; dt++) {
            const int col = dt * 8 + 2 * t;
            *(unsigned*)&Ob[col] =
                h2pack(o[mg][dt][0] * i0, o[mg][dt][1] * i0);
            *(unsigned*)&Ob[8 * DM + col] =
                h2pack(o[mg][dt][2] * i1, o[mg][dt][3] * i1);
        }
    }
}

// ---------------------------------------------------------------------------
// launch
// ---------------------------------------------------------------------------
extern "C" void kernel_launch(void* const* d_in, const int* in_sizes, int n_in,
                              void* d_out, int out_size) {
    (void)in_sizes; (void)n_in; (void)out_size;
    const float* q  = (const float*)d_in[0];
    const float* Wq = (const float*)d_in[2];
    const float* bq = (const float*)d_in[3];
    const float* Wk = (const float*)d_in[4];
    const float* bk = (const float*)d_in[5];
    const float* Wv = (const float*)d_in[6];
    const float* bv = (const float*)d_in[7];
    const float* Wo = (const float*)d_in[8];
    const float* bo = (const float*)d_in[9];
    float* out = (float*)d_out;

    __half *pXh, *pW4, *pQKV, *pAO;
    float* pb3;
    cudaGetSymbolAddress((void**)&pXh, g_Xh);
    cudaGetSymbolAddress((void**)&pW4, g_W4);
    cudaGetSymbolAddress((void**)&pb3, g_b3);
    cudaGetSymbolAddress((void**)&pQKV, g_QKV);
    cudaGetSymbolAddress((void**)&pAO, g_AO);

    cudaFuncSetAttribute(gemm_f16<1>, cudaFuncAttributeMaxDynamicSharedMemorySize,
                         SMEM_GEMM);
    cudaFuncSetAttribute(gemm_f16<0>, cudaFuncAttributeMaxDynamicSharedMemorySize,
                         SMEM_GEMM);
    cudaFuncSetAttribute(attn_f16, cudaFuncAttributeMaxDynamicSharedMemorySize,
                         SMEM_ATTN);

    f2h4<<<(NB * TT * DM) / 1024, 256>>>(q, pXh);
    f2h4<<<(DM * DM) / 1024, 256>>>(Wq, pW4 + 0 * DM * DM);
    f2h4<<<(DM * DM) / 1024, 256>>>(Wk, pW4 + 1 * DM * DM);
    f2h4<<<(DM * DM) / 1024, 256>>>(Wv, pW4 + 2 * DM * DM);
    f2h4<<<(DM * DM) / 1024, 256>>>(Wo, pW4 + 3 * DM * DM);
    bias_cat<<<12, 256>>>(bq, bk, bv, pb3);

    // fused QKV projection: Q-cols pre-scaled by 0.125*log2e for exp2 softmax
    gemm_f16<1><<<dim3(3 * DM / GBN, (NB * TT) / GBM), 128, SMEM_GEMM>>>(
        pXh, pW4, pb3, pQKV);

    attn_f16<<<dim3(TT / BQ, NB * NH), 256, SMEM_ATTN>>>(pQKV, pAO);

    gemm_f16<0><<<dim3(DM / GBN, (NB * TT) / GBM), 128, SMEM_GEMM>>>(
        pAO, pW4 + 3 * DM * DM, bo, out);
}